// round 11
// baseline (speedup 1.0000x reference)
#include <cuda_runtime.h>
#include <cuda_fp16.h>
#include <math.h>
#include <stdint.h>

#define BATCH 8
#define CIN 1024
#define CI 512
#define HW 4096     // 64*64
#define HWP 1024    // 32*32
#define WSZ 524288  // each weight matrix is 512*1024 elements

// ---- scratch (static device globals; no runtime allocation) ----
__device__ __half d_xTh[(size_t)BATCH * HW * CIN];
__device__ __half d_xpTh[(size_t)BATCH * HWP * CIN];
__device__ __half d_thetaTh[(size_t)BATCH * HW * CI];
__device__ __half d_phiTh[(size_t)BATCH * HWP * CI];
__device__ __half d_Gh[(size_t)BATCH * CI * HWP];      // [CI][HWP] per batch
__device__ __half d_attnh[(size_t)BATCH * HW * HWP];
__device__ __half d_yTh[(size_t)BATCH * HW * CI];
__device__ __half d_zTh[(size_t)BATCH * HW * CIN];     // fp16 z
__device__ __half d_w4h[4 * WSZ];
__device__ float d_psum[64][CIN];
__device__ float d_psq[64][CIN];
__device__ float d_mean[CIN];
__device__ float d_rstd[CIN];

__device__ __forceinline__ void cp16(uint32_t dst, const void* src) {
    asm volatile("cp.async.cg.shared.global [%0], [%1], 16;\n" :: "r"(dst), "l"(src));
}

// ---------------- prep kernels ----------------
__global__ void round_weights_kernel(const float* __restrict__ w0, const float* __restrict__ w1,
                                     const float* __restrict__ w2, const float* __restrict__ w3) {
    int i = blockIdx.x * blockDim.x + threadIdx.x;
    if (i >= WSZ) return;
    d_w4h[0 * WSZ + i] = __float2half_rn(w0[i]);
    d_w4h[1 * WSZ + i] = __float2half_rn(w1[i]);
    d_w4h[2 * WSZ + i] = __float2half_rn(w2[i]);
    d_w4h[3 * WSZ + i] = __float2half_rn(w3[i]);
}

// xTh[b][hw][c] = fp16(x[b][c][hw]) via 32x32 tiled transpose
__global__ void transpose_x_kernel(const float* __restrict__ x) {
    __shared__ float s[32][33];
    int b = blockIdx.z;
    int hw0 = blockIdx.x * 32, c0 = blockIdx.y * 32;
    int tx = threadIdx.x & 31, ty = threadIdx.x >> 5;  // 256 threads: 32x8
#pragma unroll
    for (int k = 0; k < 4; k++)
        s[ty + 8 * k][tx] = x[((size_t)(b * CIN) + c0 + ty + 8 * k) * HW + hw0 + tx];
    __syncthreads();
#pragma unroll
    for (int k = 0; k < 4; k++)
        d_xTh[((size_t)(b * HW) + hw0 + ty + 8 * k) * CIN + c0 + tx] =
            __float2half_rn(s[tx][ty + 8 * k]);
}

// maxpool 2x2 s2 + transpose -> xpTh[b][p][c] fp16
__global__ void maxpool_t_kernel(const float* __restrict__ x) {
    __shared__ float s[32][129];
    int b = blockIdx.z;
    int i = blockIdx.x;        // pooled row 0..31
    int c0 = blockIdx.y * 32;
    int tid = threadIdx.x;     // 256
#pragma unroll
    for (int l = 0; l < 16; l++) {
        int idx = tid + l * 256;
        int c = idx >> 7, e = idx & 127;
        s[c][e] = x[((size_t)(b * CIN) + c0 + c) * HW + i * 128 + e];
    }
    __syncthreads();
#pragma unroll
    for (int l = 0; l < 4; l++) {
        int o = tid + l * 256;
        int p = o >> 5, c = o & 31;
        float v = fmaxf(fmaxf(s[c][2 * p], s[c][2 * p + 1]),
                        fmaxf(s[c][64 + 2 * p], s[c][64 + 2 * p + 1]));
        d_xpTh[((size_t)(b * HWP) + i * 32 + p) * CIN + c0 + c] = __float2half_rn(v);
    }
}

// ---------------- fp16 tensor-core GEMM ----------------
// C[M,N] = alpha * A[M,K] . B[N,K]^T + bias;  K contiguous, fp16 in/out.
// CTA tile 128x128, 8 warps (4 along M x 2 along N), warp tile 32x64.
// BK=64 halves (128B rows). 3-stage cp.async. 2 CTAs/SM.
// BIASM: bias indexed by M (else by N).
#define NSTG 3
#define HSM_A_STAGE 16384
#define HSM_B_OFF   (NSTG * HSM_A_STAGE)
#define HSM_B_STAGE 16384
#define HSM_TOTAL   (NSTG * (HSM_A_STAGE + HSM_B_STAGE))   // 98304

template <int BIASM>
__global__ void __launch_bounds__(256, 2) hgemm(
    const __half* __restrict__ A, const __half* __restrict__ Bp,
    __half* __restrict__ C, const float* __restrict__ bias,
    int M, int N, int K, size_t sA, size_t sB, size_t sC, float alpha)
{
    extern __shared__ char smem[];
    uint32_t sb;
    asm("{ .reg .u64 t; cvta.to.shared.u64 t, %1; cvt.u32.u64 %0, t; }" : "=r"(sb) : "l"(smem));

    const int b = blockIdx.z;
    A  += (size_t)b * sA;
    Bp += (size_t)b * sB;

    const int m0 = blockIdx.y * 128;
    const int n0 = blockIdx.x * 128;
    const int tid = threadIdx.x;
    const int wid = tid >> 5;
    const int lane = tid & 31;
    const int wm = wid & 3;          // 4 warps along M -> 32 rows each
    const int wn = wid >> 2;         // 2 warps along N -> 64 cols each

    const int g = lane >> 3;
    const int rr = lane & 7;
    const int row_off = ((g & 1) << 3) + rr;
    const int chunk_g = g >> 1;

    float acc[2][8][4];
#pragma unroll
    for (int mi = 0; mi < 2; mi++)
#pragma unroll
        for (int ni = 0; ni < 8; ni++)
#pragma unroll
            for (int v = 0; v < 4; v++) acc[mi][ni][v] = 0.f;

    const int NT = K / 64;

    auto prefetch = [&](int it, int buf) {
        const int k0 = it * 64;
        uint32_t sAb = sb + buf * HSM_A_STAGE;
        uint32_t sBb = sb + HSM_B_OFF + buf * HSM_B_STAGE;
#pragma unroll
        for (int i = 0; i < 4; i++) {
            int l = tid + i * 256;
            int r = l >> 3, c = l & 7;
            cp16(sAb + r * 128 + ((c ^ (r & 7)) << 4),
                 A + (size_t)(m0 + r) * K + k0 + c * 8);
        }
#pragma unroll
        for (int i = 0; i < 4; i++) {
            int l = tid + i * 256;
            int r = l >> 3, c = l & 7;
            cp16(sBb + r * 128 + ((c ^ (r & 7)) << 4),
                 Bp + (size_t)(n0 + r) * K + k0 + c * 8);
        }
    };

    // prime NSTG-1 stages
#pragma unroll
    for (int p = 0; p < NSTG - 1; p++) {
        if (p < NT) prefetch(p, p);
        asm volatile("cp.async.commit_group;\n" ::);
    }

    int buf = 0;
    for (int it = 0; it < NT; it++) {
        if (it + NSTG - 1 < NT) {
            int pb = it + NSTG - 1;
            prefetch(pb, pb % NSTG);
        }
        asm volatile("cp.async.commit_group;\n" ::);
        asm volatile("cp.async.wait_group %0;\n" :: "n"(NSTG - 1));
        __syncthreads();

        const uint32_t sA = sb + buf * HSM_A_STAGE;
        const uint32_t sB = sb + HSM_B_OFF + buf * HSM_B_STAGE;

#pragma unroll
        for (int kk = 0; kk < 4; kk++) {
            uint32_t af[2][4], bf[4][4];
#pragma unroll
            for (int mi = 0; mi < 2; mi++) {
                int m_loc = wm * 32 + mi * 16 + row_off;
                int chunk = kk * 2 + chunk_g;
                uint32_t addr = sA + m_loc * 128 + ((chunk ^ (m_loc & 7)) << 4);
                asm volatile("ldmatrix.sync.aligned.m8n8.x4.shared.b16 {%0,%1,%2,%3}, [%4];"
                             : "=r"(af[mi][0]), "=r"(af[mi][1]),
                               "=r"(af[mi][2]), "=r"(af[mi][3])
                             : "r"(addr));
            }
#pragma unroll
            for (int np = 0; np < 4; np++) {
                int n_loc = wn * 64 + np * 16 + row_off;
                int chunk = kk * 2 + chunk_g;
                uint32_t addr = sB + n_loc * 128 + ((chunk ^ (n_loc & 7)) << 4);
                asm volatile("ldmatrix.sync.aligned.m8n8.x4.shared.b16 {%0,%1,%2,%3}, [%4];"
                             : "=r"(bf[np][0]), "=r"(bf[np][1]),
                               "=r"(bf[np][2]), "=r"(bf[np][3])
                             : "r"(addr));
            }
#pragma unroll
            for (int mi = 0; mi < 2; mi++)
#pragma unroll
                for (int ni = 0; ni < 8; ni++) {
                    uint32_t b0 = bf[ni >> 1][(ni & 1)];
                    uint32_t b1 = bf[ni >> 1][2 + (ni & 1)];
                    asm volatile(
                        "mma.sync.aligned.m16n8k16.row.col.f32.f16.f16.f32 "
                        "{%0,%1,%2,%3}, {%4,%5,%6,%7}, {%8,%9}, {%0,%1,%2,%3};\n"
                        : "+f"(acc[mi][ni][0]), "+f"(acc[mi][ni][1]),
                          "+f"(acc[mi][ni][2]), "+f"(acc[mi][ni][3])
                        : "r"(af[mi][0]), "r"(af[mi][1]), "r"(af[mi][2]), "r"(af[mi][3]),
                          "r"(b0), "r"(b1));
                }
        }
        __syncthreads();
        if (++buf == NSTG) buf = 0;
    }

    // ---- epilogue ----
    C += (size_t)b * sC;
#pragma unroll
    for (int mi = 0; mi < 2; mi++) {
        int m = m0 + wm * 32 + mi * 16 + (lane >> 2);
        float bm0 = 0.f, bm1 = 0.f;
        if (BIASM && bias) { bm0 = bias[m]; bm1 = bias[m + 8]; }
#pragma unroll
        for (int ni = 0; ni < 8; ni++) {
            int n = n0 + wn * 64 + ni * 8 + (lane & 3) * 2;
            float v0 = acc[mi][ni][0] * alpha;
            float v1 = acc[mi][ni][1] * alpha;
            float v2 = acc[mi][ni][2] * alpha;
            float v3 = acc[mi][ni][3] * alpha;
            if (BIASM) {
                v0 += bm0; v1 += bm0; v2 += bm1; v3 += bm1;
            } else if (bias) {
                float bn0 = bias[n], bn1 = bias[n + 1];
                v0 += bn0; v1 += bn1; v2 += bn0; v3 += bn1;
            }
            *(__half2*)&C[(size_t)m * N + n] = __floats2half2_rn(v0, v1);
            *(__half2*)&C[(size_t)(m + 8) * N + n] = __floats2half2_rn(v2, v3);
        }
    }
}

// ---------------- row softmax over d_attnh (rows of 1024 fp16) ----------------
__global__ void softmax_kernel() {
    size_t row = blockIdx.x;
    uint2* p = (uint2*)(d_attnh + row * HWP);
    int tid = threadIdx.x;  // 256 threads, 4 halves each
    uint2 u = p[tid];
    float2 f01 = __half22float2(*(__half2*)&u.x);
    float2 f23 = __half22float2(*(__half2*)&u.y);
    float mx = fmaxf(fmaxf(f01.x, f01.y), fmaxf(f23.x, f23.y));
#pragma unroll
    for (int o = 16; o > 0; o >>= 1) mx = fmaxf(mx, __shfl_xor_sync(0xffffffffu, mx, o));
    __shared__ float sm[8], sv[8];
    if ((tid & 31) == 0) sm[tid >> 5] = mx;
    __syncthreads();
    if (tid == 0) {
        float t = sm[0];
        for (int i = 1; i < 8; i++) t = fmaxf(t, sm[i]);
        sm[0] = t;
    }
    __syncthreads();
    mx = sm[0];
    f01.x = __expf(f01.x - mx); f01.y = __expf(f01.y - mx);
    f23.x = __expf(f23.x - mx); f23.y = __expf(f23.y - mx);
    float s = f01.x + f01.y + f23.x + f23.y;
#pragma unroll
    for (int o = 16; o > 0; o >>= 1) s += __shfl_xor_sync(0xffffffffu, s, o);
    if ((tid & 31) == 0) sv[tid >> 5] = s;
    __syncthreads();
    if (tid == 0) {
        float t = 0.f;
        for (int i = 0; i < 8; i++) t += sv[i];
        sv[0] = t;
    }
    __syncthreads();
    float inv = 1.f / sv[0];
    __half2 h0 = __floats2half2_rn(f01.x * inv, f01.y * inv);
    __half2 h1 = __floats2half2_rn(f23.x * inv, f23.y * inv);
    u.x = *(uint32_t*)&h0; u.y = *(uint32_t*)&h1;
    p[tid] = u;
}

// ---------------- BN stats over zTh fp16 [B*HW][CIN] ----------------
__global__ void bn_partial_kernel() {
    int c2 = blockIdx.x * 128 + (threadIdx.x >> 1);  // channel pair base handled below
    // simpler: each thread handles one channel, read as half
    int c = blockIdx.x * 256 + threadIdx.x;
    int rb = blockIdx.y;  // 0..63, 512 rows each
    float s = 0.f, sq = 0.f;
    const __half* base = d_zTh + (size_t)rb * 512 * CIN + c;
    for (int r = 0; r < 512; r++) {
        float v = __half2float(base[(size_t)r * CIN]);
        s += v;
        sq += v * v;
    }
    d_psum[rb][c] = s;
    d_psq[rb][c] = sq;
    (void)c2;
}

__global__ void bn_final_kernel() {
    int c = blockIdx.x * 256 + threadIdx.x;
    float s = 0.f, sq = 0.f;
    for (int i = 0; i < 64; i++) { s += d_psum[i][c]; sq += d_psq[i][c]; }
    const float inv_n = 1.0f / (float)(BATCH * HW);
    float mean = s * inv_n;
    float var = sq * inv_n - mean * mean;
    d_mean[c] = mean;
    d_rstd[c] = rsqrtf(var + 1e-5f);
}

// ---------------- final: out[b][c][hw] = x + norm(zTh[b][hw][c]) ----------------
__global__ void final_kernel(const float* __restrict__ x,
                             const float* __restrict__ gamma,
                             const float* __restrict__ beta,
                             float* __restrict__ out) {
    __shared__ float s[32][33];
    int b = blockIdx.z;
    int hw0 = blockIdx.x * 32, c0 = blockIdx.y * 32;
    int tx = threadIdx.x & 31, ty = threadIdx.x >> 5;
#pragma unroll
    for (int k = 0; k < 4; k++)
        s[ty + 8 * k][tx] =
            __half2float(d_zTh[((size_t)(b * HW) + hw0 + ty + 8 * k) * CIN + c0 + tx]);
    __syncthreads();
#pragma unroll
    for (int k = 0; k < 4; k++) {
        int c = c0 + ty + 8 * k;
        size_t o = ((size_t)(b * CIN) + c) * HW + hw0 + tx;
        float sc = d_rstd[c] * gamma[c];
        float off = beta[c] - d_mean[c] * sc;
        out[o] = x[o] + s[tx][ty + 8 * k] * sc + off;
    }
}

extern "C" void kernel_launch(void* const* d_in, const int* in_sizes, int n_in,
                              void* d_out, int out_size) {
    const float* x       = (const float*)d_in[0];
    const float* theta_b = (const float*)d_in[2];
    const float* phi_b   = (const float*)d_in[4];
    const float* g_b     = (const float*)d_in[6];
    const float* wz_b    = (const float*)d_in[8];
    const float* gamma   = (const float*)d_in[9];
    const float* beta    = (const float*)d_in[10];
    float* out = (float*)d_out;

    __half *xTh, *xpTh, *thetaTh, *phiTh, *Gh, *attnh, *yTh, *zTh, *w4h;
    cudaGetSymbolAddress((void**)&xTh, d_xTh);
    cudaGetSymbolAddress((void**)&xpTh, d_xpTh);
    cudaGetSymbolAddress((void**)&thetaTh, d_thetaTh);
    cudaGetSymbolAddress((void**)&phiTh, d_phiTh);
    cudaGetSymbolAddress((void**)&Gh, d_Gh);
    cudaGetSymbolAddress((void**)&attnh, d_attnh);
    cudaGetSymbolAddress((void**)&yTh, d_yTh);
    cudaGetSymbolAddress((void**)&zTh, d_zTh);
    cudaGetSymbolAddress((void**)&w4h, d_w4h);

    cudaFuncSetAttribute(hgemm<0>, cudaFuncAttributeMaxDynamicSharedMemorySize, HSM_TOTAL);
    cudaFuncSetAttribute(hgemm<1>, cudaFuncAttributeMaxDynamicSharedMemorySize, HSM_TOTAL);

    // 0. prep
    round_weights_kernel<<<(WSZ + 255) / 256, 256>>>(
        (const float*)d_in[1], (const float*)d_in[3], (const float*)d_in[5], (const float*)d_in[7]);
    transpose_x_kernel<<<dim3(HW / 32, CIN / 32, BATCH), 256>>>(x);
    maxpool_t_kernel<<<dim3(32, CIN / 32, BATCH), 256>>>(x);

    // 1. thetaT[HW,CI] = xT . theta_w^T + theta_b (per N)
    hgemm<0><<<dim3(CI / 128, HW / 128, BATCH), 256, HSM_TOTAL>>>(
        xTh, w4h + 0 * WSZ, thetaTh, theta_b,
        HW, CI, CIN, (size_t)HW * CIN, 0, (size_t)HW * CI, 1.0f);

    // 2. phiT[HWP,CI] = xpT . phi_w^T + phi_b (per N)
    hgemm<0><<<dim3(CI / 128, HWP / 128, BATCH), 256, HSM_TOTAL>>>(
        xpTh, w4h + 1 * WSZ, phiTh, phi_b,
        HWP, CI, CIN, (size_t)HWP * CIN, 0, (size_t)HWP * CI, 1.0f);

    // 3. G[CI,HWP] = g_w . xpT^T + g_b (per M)
    hgemm<1><<<dim3(HWP / 128, CI / 128, BATCH), 256, HSM_TOTAL>>>(
        w4h + 2 * WSZ, xpTh, Gh, g_b,
        CI, HWP, CIN, 0, (size_t)HWP * CIN, (size_t)CI * HWP, 1.0f);

    // 4. attn[HW,HWP] = thetaT . phiT^T * scale
    const float scale = 1.0f / sqrtf((float)CI);
    hgemm<0><<<dim3(HWP / 128, HW / 128, BATCH), 256, HSM_TOTAL>>>(
        thetaTh, phiTh, attnh, nullptr,
        HW, HWP, CI, (size_t)HW * CI, (size_t)HWP * CI, (size_t)HW * HWP, scale);

    // 5. softmax
    softmax_kernel<<<BATCH * HW, 256>>>();

    // 6. yT[HW,CI] = attn . G^T
    hgemm<0><<<dim3(CI / 128, HW / 128, BATCH), 256, HSM_TOTAL>>>(
        attnh, Gh, yTh, nullptr,
        HW, CI, HWP, (size_t)HW * HWP, (size_t)CI * HWP, (size_t)HW * CI, 1.0f);

    // 7. zTh[HW,CIN] = yT . wz_w^T + wz_b (per N), fp16 out
    hgemm<0><<<dim3(CIN / 128, HW / 128, BATCH), 256, HSM_TOTAL>>>(
        yTh, w4h + 3 * WSZ, zTh, wz_b,
        HW, CIN, CI, (size_t)HW * CI, 0, (size_t)HW * CIN, 1.0f);

    // 8. BN stats
    bn_partial_kernel<<<dim3(CIN / 256, 64), 256>>>();
    bn_final_kernel<<<CIN / 256, 256>>>();

    // 9. out = x + gamma*(zTh-mean)*rstd + beta (transpose back)
    final_kernel<<<dim3(HW / 32, CIN / 32, BATCH), 256>>>(x, gamma, beta, out);
}

// round 12
// speedup vs baseline: 1.4702x; 1.4702x over previous
#include <cuda_runtime.h>
#include <cuda_fp16.h>
#include <math.h>
#include <stdint.h>

#define BATCH 8
#define CIN 1024
#define CI 512
#define HW 4096     // 64*64
#define HWP 1024    // 32*32
#define WSZ 524288  // each weight matrix is 512*1024 elements

// ---- scratch (static device globals; no runtime allocation) ----
__device__ __half d_xTh[(size_t)BATCH * HW * CIN];
__device__ __half d_xpTh[(size_t)BATCH * HWP * CIN];
__device__ __half d_thetaTh[(size_t)BATCH * HW * CI];
__device__ __half d_phiTh[(size_t)BATCH * HWP * CI];
__device__ __half d_Gh[(size_t)BATCH * CI * HWP];      // [CI][HWP] per batch
__device__ __half d_attnh[(size_t)BATCH * HW * HWP];
__device__ __half d_yTh[(size_t)BATCH * HW * CI];
__device__ __half d_zTh[(size_t)BATCH * HW * CIN];     // fp16 z
__device__ __half d_w4h[4 * WSZ];
__device__ float d_psum[64][CIN];
__device__ float d_psq[64][CIN];
__device__ float d_mean[CIN];
__device__ float d_rstd[CIN];

__device__ __forceinline__ void cp16(uint32_t dst, const void* src) {
    asm volatile("cp.async.cg.shared.global [%0], [%1], 16;\n" :: "r"(dst), "l"(src));
}

// ---------------- prep kernels ----------------
__global__ void round_weights_kernel(const float* __restrict__ w0, const float* __restrict__ w1,
                                     const float* __restrict__ w2, const float* __restrict__ w3) {
    int i = blockIdx.x * blockDim.x + threadIdx.x;
    if (i >= WSZ) return;
    d_w4h[0 * WSZ + i] = __float2half_rn(w0[i]);
    d_w4h[1 * WSZ + i] = __float2half_rn(w1[i]);
    d_w4h[2 * WSZ + i] = __float2half_rn(w2[i]);
    d_w4h[3 * WSZ + i] = __float2half_rn(w3[i]);
}

// xTh[b][hw][c] = fp16(x[b][c][hw]) via 32x32 tiled transpose
__global__ void transpose_x_kernel(const float* __restrict__ x) {
    __shared__ float s[32][33];
    int b = blockIdx.z;
    int hw0 = blockIdx.x * 32, c0 = blockIdx.y * 32;
    int tx = threadIdx.x & 31, ty = threadIdx.x >> 5;  // 256 threads: 32x8
#pragma unroll
    for (int k = 0; k < 4; k++)
        s[ty + 8 * k][tx] = x[((size_t)(b * CIN) + c0 + ty + 8 * k) * HW + hw0 + tx];
    __syncthreads();
#pragma unroll
    for (int k = 0; k < 4; k++)
        d_xTh[((size_t)(b * HW) + hw0 + ty + 8 * k) * CIN + c0 + tx] =
            __float2half_rn(s[tx][ty + 8 * k]);
}

// maxpool from xTh: xpTh[b][p][c] = max over 4 spatial neighbors (rows of xTh)
__global__ void maxpool_t_kernel() {
    int p = blockIdx.x;        // pooled index 0..HWP-1
    int b = blockIdx.y;
    int pi = p >> 5, pj = p & 31;
    size_t base = (size_t)b * HW;
    const __half2* r0 = (const __half2*)(d_xTh + (base + (size_t)(2 * pi) * 64 + 2 * pj) * CIN);
    const __half2* r1 = (const __half2*)(d_xTh + (base + (size_t)(2 * pi) * 64 + 2 * pj + 1) * CIN);
    const __half2* r2 = (const __half2*)(d_xTh + (base + (size_t)(2 * pi + 1) * 64 + 2 * pj) * CIN);
    const __half2* r3 = (const __half2*)(d_xTh + (base + (size_t)(2 * pi + 1) * 64 + 2 * pj + 1) * CIN);
    __half2* dst = (__half2*)(d_xpTh + ((size_t)b * HWP + p) * CIN);
    for (int c = threadIdx.x; c < CIN / 2; c += blockDim.x) {
        __half2 v = __hmax2(__hmax2(r0[c], r1[c]), __hmax2(r2[c], r3[c]));
        dst[c] = v;
    }
}

// ---------------- fp16 tensor-core GEMM ----------------
// C[M,N] = alpha * A[M,K] . B[N,K]^T + bias;  K contiguous, fp16 in/out.
// CTA tile 128x128, 4 warps (2x2), warp tile 64x64, BK=64 halves (128B rows).
// 3-stage cp.async, 2 CTAs/SM.  BIASM: bias indexed by M (else by N).
#define NSTG 3
#define HSM_A_STAGE 16384
#define HSM_B_OFF   (NSTG * HSM_A_STAGE)
#define HSM_B_STAGE 16384
#define HSM_TOTAL   (NSTG * (HSM_A_STAGE + HSM_B_STAGE))   // 98304

template <int BIASM>
__global__ void __launch_bounds__(128, 2) hgemm(
    const __half* __restrict__ A, const __half* __restrict__ Bp,
    __half* __restrict__ C, const float* __restrict__ bias,
    int M, int N, int K, size_t sA, size_t sB, size_t sC, float alpha)
{
    extern __shared__ char smem[];
    uint32_t sb;
    asm("{ .reg .u64 t; cvta.to.shared.u64 t, %1; cvt.u32.u64 %0, t; }" : "=r"(sb) : "l"(smem));

    const int b = blockIdx.z;
    A  += (size_t)b * sA;
    Bp += (size_t)b * sB;

    const int m0 = blockIdx.y * 128;
    const int n0 = blockIdx.x * 128;
    const int tid = threadIdx.x;
    const int wid = tid >> 5;
    const int lane = tid & 31;
    const int wm = wid & 1;          // 2 warps along M -> 64 rows each
    const int wn = wid >> 1;         // 2 warps along N -> 64 cols each

    const int g = lane >> 3;
    const int rr = lane & 7;
    const int row_off = ((g & 1) << 3) + rr;
    const int chunk_g = g >> 1;

    float acc[4][8][4];
#pragma unroll
    for (int mi = 0; mi < 4; mi++)
#pragma unroll
        for (int ni = 0; ni < 8; ni++)
#pragma unroll
            for (int v = 0; v < 4; v++) acc[mi][ni][v] = 0.f;

    const int NT = K / 64;

    auto prefetch = [&](int it, int buf) {
        const int k0 = it * 64;
        uint32_t sAb = sb + buf * HSM_A_STAGE;
        uint32_t sBb = sb + HSM_B_OFF + buf * HSM_B_STAGE;
#pragma unroll
        for (int i = 0; i < 8; i++) {
            int l = tid + i * 128;
            int r = l >> 3, c = l & 7;
            cp16(sAb + r * 128 + ((c ^ (r & 7)) << 4),
                 A + (size_t)(m0 + r) * K + k0 + c * 8);
        }
#pragma unroll
        for (int i = 0; i < 8; i++) {
            int l = tid + i * 128;
            int r = l >> 3, c = l & 7;
            cp16(sBb + r * 128 + ((c ^ (r & 7)) << 4),
                 Bp + (size_t)(n0 + r) * K + k0 + c * 8);
        }
    };

    // prime NSTG-1 stages
#pragma unroll
    for (int p = 0; p < NSTG - 1; p++) {
        if (p < NT) prefetch(p, p);
        asm volatile("cp.async.commit_group;\n" ::);
    }

    int buf = 0;
    for (int it = 0; it < NT; it++) {
        if (it + NSTG - 1 < NT) {
            int pb = it + NSTG - 1;
            prefetch(pb, pb % NSTG);
        }
        asm volatile("cp.async.commit_group;\n" ::);
        asm volatile("cp.async.wait_group %0;\n" :: "n"(NSTG - 1));
        __syncthreads();

        const uint32_t sA = sb + buf * HSM_A_STAGE;
        const uint32_t sB = sb + HSM_B_OFF + buf * HSM_B_STAGE;

#pragma unroll
        for (int kk = 0; kk < 4; kk++) {
            uint32_t af[4][4], bf[4][4];
#pragma unroll
            for (int mi = 0; mi < 4; mi++) {
                int m_loc = wm * 64 + mi * 16 + row_off;
                int chunk = kk * 2 + chunk_g;
                uint32_t addr = sA + m_loc * 128 + ((chunk ^ (m_loc & 7)) << 4);
                asm volatile("ldmatrix.sync.aligned.m8n8.x4.shared.b16 {%0,%1,%2,%3}, [%4];"
                             : "=r"(af[mi][0]), "=r"(af[mi][1]),
                               "=r"(af[mi][2]), "=r"(af[mi][3])
                             : "r"(addr));
            }
#pragma unroll
            for (int np = 0; np < 4; np++) {
                int n_loc = wn * 64 + np * 16 + row_off;
                int chunk = kk * 2 + chunk_g;
                uint32_t addr = sB + n_loc * 128 + ((chunk ^ (n_loc & 7)) << 4);
                asm volatile("ldmatrix.sync.aligned.m8n8.x4.shared.b16 {%0,%1,%2,%3}, [%4];"
                             : "=r"(bf[np][0]), "=r"(bf[np][1]),
                               "=r"(bf[np][2]), "=r"(bf[np][3])
                             : "r"(addr));
            }
#pragma unroll
            for (int mi = 0; mi < 4; mi++)
#pragma unroll
                for (int ni = 0; ni < 8; ni++) {
                    uint32_t b0 = bf[ni >> 1][(ni & 1)];
                    uint32_t b1 = bf[ni >> 1][2 + (ni & 1)];
                    asm volatile(
                        "mma.sync.aligned.m16n8k16.row.col.f32.f16.f16.f32 "
                        "{%0,%1,%2,%3}, {%4,%5,%6,%7}, {%8,%9}, {%0,%1,%2,%3};\n"
                        : "+f"(acc[mi][ni][0]), "+f"(acc[mi][ni][1]),
                          "+f"(acc[mi][ni][2]), "+f"(acc[mi][ni][3])
                        : "r"(af[mi][0]), "r"(af[mi][1]), "r"(af[mi][2]), "r"(af[mi][3]),
                          "r"(b0), "r"(b1));
                }
        }
        __syncthreads();
        if (++buf == NSTG) buf = 0;
    }

    // ---- epilogue ----
    C += (size_t)b * sC;
#pragma unroll
    for (int mi = 0; mi < 4; mi++) {
        int m = m0 + wm * 64 + mi * 16 + (lane >> 2);
        float bm0 = 0.f, bm1 = 0.f;
        if (BIASM && bias) { bm0 = bias[m]; bm1 = bias[m + 8]; }
#pragma unroll
        for (int ni = 0; ni < 8; ni++) {
            int n = n0 + wn * 64 + ni * 8 + (lane & 3) * 2;
            float v0 = acc[mi][ni][0] * alpha;
            float v1 = acc[mi][ni][1] * alpha;
            float v2 = acc[mi][ni][2] * alpha;
            float v3 = acc[mi][ni][3] * alpha;
            if (BIASM) {
                v0 += bm0; v1 += bm0; v2 += bm1; v3 += bm1;
            } else if (bias) {
                float bn0 = bias[n], bn1 = bias[n + 1];
                v0 += bn0; v1 += bn1; v2 += bn0; v3 += bn1;
            }
            *(__half2*)&C[(size_t)m * N + n] = __floats2half2_rn(v0, v1);
            *(__half2*)&C[(size_t)(m + 8) * N + n] = __floats2half2_rn(v2, v3);
        }
    }
}

// ---------------- row softmax over d_attnh (rows of 1024 fp16) ----------------
__global__ void softmax_kernel() {
    size_t row = blockIdx.x;
    uint2* p = (uint2*)(d_attnh + row * HWP);
    int tid = threadIdx.x;  // 256 threads, 4 halves each
    uint2 u = p[tid];
    float2 f01 = __half22float2(*(__half2*)&u.x);
    float2 f23 = __half22float2(*(__half2*)&u.y);
    float mx = fmaxf(fmaxf(f01.x, f01.y), fmaxf(f23.x, f23.y));
#pragma unroll
    for (int o = 16; o > 0; o >>= 1) mx = fmaxf(mx, __shfl_xor_sync(0xffffffffu, mx, o));
    __shared__ float sm[8], sv[8];
    if ((tid & 31) == 0) sm[tid >> 5] = mx;
    __syncthreads();
    if (tid == 0) {
        float t = sm[0];
        for (int i = 1; i < 8; i++) t = fmaxf(t, sm[i]);
        sm[0] = t;
    }
    __syncthreads();
    mx = sm[0];
    f01.x = __expf(f01.x - mx); f01.y = __expf(f01.y - mx);
    f23.x = __expf(f23.x - mx); f23.y = __expf(f23.y - mx);
    float s = f01.x + f01.y + f23.x + f23.y;
#pragma unroll
    for (int o = 16; o > 0; o >>= 1) s += __shfl_xor_sync(0xffffffffu, s, o);
    if ((tid & 31) == 0) sv[tid >> 5] = s;
    __syncthreads();
    if (tid == 0) {
        float t = 0.f;
        for (int i = 0; i < 8; i++) t += sv[i];
        sv[0] = t;
    }
    __syncthreads();
    float inv = 1.f / sv[0];
    __half2 h0 = __floats2half2_rn(f01.x * inv, f01.y * inv);
    __half2 h1 = __floats2half2_rn(f23.x * inv, f23.y * inv);
    u.x = *(uint32_t*)&h0; u.y = *(uint32_t*)&h1;
    p[tid] = u;
}

// ---------------- BN stats over zTh fp16 [B*HW][CIN] ----------------
__global__ void bn_partial_kernel() {
    int c = blockIdx.x * 256 + threadIdx.x;
    int rb = blockIdx.y;  // 0..63, 512 rows each
    float s = 0.f, sq = 0.f;
    const __half* base = d_zTh + (size_t)rb * 512 * CIN + c;
    for (int r = 0; r < 512; r++) {
        float v = __half2float(base[(size_t)r * CIN]);
        s += v;
        sq += v * v;
    }
    d_psum[rb][c] = s;
    d_psq[rb][c] = sq;
}

__global__ void bn_final_kernel() {
    int c = blockIdx.x * 256 + threadIdx.x;
    float s = 0.f, sq = 0.f;
    for (int i = 0; i < 64; i++) { s += d_psum[i][c]; sq += d_psq[i][c]; }
    const float inv_n = 1.0f / (float)(BATCH * HW);
    float mean = s * inv_n;
    float var = sq * inv_n - mean * mean;
    d_mean[c] = mean;
    d_rstd[c] = rsqrtf(var + 1e-5f);
}

// ---------------- final: out[b][c][hw] = x + norm(zTh[b][hw][c]) ----------------
__global__ void final_kernel(const float* __restrict__ x,
                             const float* __restrict__ gamma,
                             const float* __restrict__ beta,
                             float* __restrict__ out) {
    __shared__ float s[32][33];
    int b = blockIdx.z;
    int hw0 = blockIdx.x * 32, c0 = blockIdx.y * 32;
    int tx = threadIdx.x & 31, ty = threadIdx.x >> 5;
#pragma unroll
    for (int k = 0; k < 4; k++)
        s[ty + 8 * k][tx] =
            __half2float(d_zTh[((size_t)(b * HW) + hw0 + ty + 8 * k) * CIN + c0 + tx]);
    __syncthreads();
#pragma unroll
    for (int k = 0; k < 4; k++) {
        int c = c0 + ty + 8 * k;
        size_t o = ((size_t)(b * CIN) + c) * HW + hw0 + tx;
        float sc = d_rstd[c] * gamma[c];
        float off = beta[c] - d_mean[c] * sc;
        out[o] = x[o] + s[tx][ty + 8 * k] * sc + off;
    }
}

extern "C" void kernel_launch(void* const* d_in, const int* in_sizes, int n_in,
                              void* d_out, int out_size) {
    const float* x       = (const float*)d_in[0];
    const float* theta_b = (const float*)d_in[2];
    const float* phi_b   = (const float*)d_in[4];
    const float* g_b     = (const float*)d_in[6];
    const float* wz_b    = (const float*)d_in[8];
    const float* gamma   = (const float*)d_in[9];
    const float* beta    = (const float*)d_in[10];
    float* out = (float*)d_out;

    __half *xTh, *xpTh, *thetaTh, *phiTh, *Gh, *attnh, *yTh, *zTh, *w4h;
    cudaGetSymbolAddress((void**)&xTh, d_xTh);
    cudaGetSymbolAddress((void**)&xpTh, d_xpTh);
    cudaGetSymbolAddress((void**)&thetaTh, d_thetaTh);
    cudaGetSymbolAddress((void**)&phiTh, d_phiTh);
    cudaGetSymbolAddress((void**)&Gh, d_Gh);
    cudaGetSymbolAddress((void**)&attnh, d_attnh);
    cudaGetSymbolAddress((void**)&yTh, d_yTh);
    cudaGetSymbolAddress((void**)&zTh, d_zTh);
    cudaGetSymbolAddress((void**)&w4h, d_w4h);

    cudaFuncSetAttribute(hgemm<0>, cudaFuncAttributeMaxDynamicSharedMemorySize, HSM_TOTAL);
    cudaFuncSetAttribute(hgemm<1>, cudaFuncAttributeMaxDynamicSharedMemorySize, HSM_TOTAL);

    // 0. prep
    round_weights_kernel<<<(WSZ + 255) / 256, 256>>>(
        (const float*)d_in[1], (const float*)d_in[3], (const float*)d_in[5], (const float*)d_in[7]);
    transpose_x_kernel<<<dim3(HW / 32, CIN / 32, BATCH), 256>>>(x);
    maxpool_t_kernel<<<dim3(HWP, BATCH), 256>>>();

    // 1. thetaT[HW,CI] = xT . theta_w^T + theta_b (per N)
    hgemm<0><<<dim3(CI / 128, HW / 128, BATCH), 128, HSM_TOTAL>>>(
        xTh, w4h + 0 * WSZ, thetaTh, theta_b,
        HW, CI, CIN, (size_t)HW * CIN, 0, (size_t)HW * CI, 1.0f);

    // 2. phiT[HWP,CI] = xpT . phi_w^T + phi_b (per N)
    hgemm<0><<<dim3(CI / 128, HWP / 128, BATCH), 128, HSM_TOTAL>>>(
        xpTh, w4h + 1 * WSZ, phiTh, phi_b,
        HWP, CI, CIN, (size_t)HWP * CIN, 0, (size_t)HWP * CI, 1.0f);

    // 3. G[CI,HWP] = g_w . xpT^T + g_b (per M)
    hgemm<1><<<dim3(HWP / 128, CI / 128, BATCH), 128, HSM_TOTAL>>>(
        w4h + 2 * WSZ, xpTh, Gh, g_b,
        CI, HWP, CIN, 0, (size_t)HWP * CIN, (size_t)CI * HWP, 1.0f);

    // 4. attn[HW,HWP] = thetaT . phiT^T * scale
    const float scale = 1.0f / sqrtf((float)CI);
    hgemm<0><<<dim3(HWP / 128, HW / 128, BATCH), 128, HSM_TOTAL>>>(
        thetaTh, phiTh, attnh, nullptr,
        HW, HWP, CI, (size_t)HW * CI, (size_t)HWP * CI, (size_t)HW * HWP, scale);

    // 5. softmax
    softmax_kernel<<<BATCH * HW, 256>>>();

    // 6. yT[HW,CI] = attn . G^T
    hgemm<0><<<dim3(CI / 128, HW / 128, BATCH), 128, HSM_TOTAL>>>(
        attnh, Gh, yTh, nullptr,
        HW, CI, HWP, (size_t)HW * HWP, (size_t)CI * HWP, (size_t)HW * CI, 1.0f);

    // 7. zTh[HW,CIN] = yT . wz_w^T + wz_b (per N), fp16 out
    hgemm<0><<<dim3(CIN / 128, HW / 128, BATCH), 128, HSM_TOTAL>>>(
        yTh, w4h + 3 * WSZ, zTh, wz_b,
        HW, CIN, CI, (size_t)HW * CI, 0, (size_t)HW * CIN, 1.0f);

    // 8. BN stats
    bn_partial_kernel<<<dim3(CIN / 256, 64), 256>>>();
    bn_final_kernel<<<CIN / 256, 256>>>();

    // 9. out = x + gamma*(zTh-mean)*rstd + beta (transpose back)
    final_kernel<<<dim3(HW / 32, CIN / 32, BATCH), 256>>>(x, gamma, beta, out);
}

// round 13
// speedup vs baseline: 1.5758x; 1.0719x over previous
#include <cuda_runtime.h>
#include <cuda_fp16.h>
#include <math.h>
#include <stdint.h>

#define BATCH 8
#define CIN 1024
#define CI 512
#define HW 4096     // 64*64
#define HWP 1024    // 32*32
#define WSZ 524288  // each weight matrix is 512*1024 elements

// ---- scratch (static device globals; no runtime allocation) ----
__device__ __half d_xTh[(size_t)BATCH * HW * CIN];
__device__ __half d_xpTh[(size_t)BATCH * HWP * CIN];
__device__ __half d_thetaTh[(size_t)BATCH * HW * CI];
__device__ __half d_phiTh[(size_t)BATCH * HWP * CI];
__device__ __half d_Gh[(size_t)BATCH * CI * HWP];      // [CI][HWP] per batch
__device__ __half d_attnh[(size_t)BATCH * HW * HWP];   // exp(scores), unnormalized
__device__ __half d_yTh[(size_t)BATCH * HW * CI];
__device__ __half d_zTh[(size_t)BATCH * HW * CIN];     // fp16 z
__device__ __half d_w4h[4 * WSZ];
__device__ float d_rowsum[(size_t)BATCH * HW];
__device__ float d_bnsum[CIN];
__device__ float d_bnsq[CIN];
__device__ float d_mean[CIN];
__device__ float d_rstd[CIN];

__device__ __forceinline__ void cp16(uint32_t dst, const void* src) {
    asm volatile("cp.async.cg.shared.global [%0], [%1], 16;\n" :: "r"(dst), "l"(src));
}

// ---------------- prep kernels ----------------
__global__ void zero_kernel() {
    int i = blockIdx.x * 256 + threadIdx.x;
    if (i < BATCH * HW) d_rowsum[i] = 0.f;
    if (i < CIN) { d_bnsum[i] = 0.f; d_bnsq[i] = 0.f; }
}

__global__ void round_weights_kernel(const float* __restrict__ w0, const float* __restrict__ w1,
                                     const float* __restrict__ w2, const float* __restrict__ w3) {
    int i = blockIdx.x * blockDim.x + threadIdx.x;
    if (i >= WSZ) return;
    d_w4h[0 * WSZ + i] = __float2half_rn(w0[i]);
    d_w4h[1 * WSZ + i] = __float2half_rn(w1[i]);
    d_w4h[2 * WSZ + i] = __float2half_rn(w2[i]);
    d_w4h[3 * WSZ + i] = __float2half_rn(w3[i]);
}

// xTh[b][hw][c] = fp16(x[b][c][hw]) via 32x32 tiled transpose
__global__ void transpose_x_kernel(const float* __restrict__ x) {
    __shared__ float s[32][33];
    int b = blockIdx.z;
    int hw0 = blockIdx.x * 32, c0 = blockIdx.y * 32;
    int tx = threadIdx.x & 31, ty = threadIdx.x >> 5;  // 256 threads: 32x8
#pragma unroll
    for (int k = 0; k < 4; k++)
        s[ty + 8 * k][tx] = x[((size_t)(b * CIN) + c0 + ty + 8 * k) * HW + hw0 + tx];
    __syncthreads();
#pragma unroll
    for (int k = 0; k < 4; k++)
        d_xTh[((size_t)(b * HW) + hw0 + ty + 8 * k) * CIN + c0 + tx] =
            __float2half_rn(s[tx][ty + 8 * k]);
}

// maxpool from xTh: xpTh[b][p][c] = max over 4 spatial neighbors (rows of xTh)
__global__ void maxpool_t_kernel() {
    int p = blockIdx.x;        // pooled index 0..HWP-1
    int b = blockIdx.y;
    int pi = p >> 5, pj = p & 31;
    size_t base = (size_t)b * HW;
    const __half2* r0 = (const __half2*)(d_xTh + (base + (size_t)(2 * pi) * 64 + 2 * pj) * CIN);
    const __half2* r1 = (const __half2*)(d_xTh + (base + (size_t)(2 * pi) * 64 + 2 * pj + 1) * CIN);
    const __half2* r2 = (const __half2*)(d_xTh + (base + (size_t)(2 * pi + 1) * 64 + 2 * pj) * CIN);
    const __half2* r3 = (const __half2*)(d_xTh + (base + (size_t)(2 * pi + 1) * 64 + 2 * pj + 1) * CIN);
    __half2* dst = (__half2*)(d_xpTh + ((size_t)b * HWP + p) * CIN);
    for (int c = threadIdx.x; c < CIN / 2; c += blockDim.x) {
        __half2 v = __hmax2(__hmax2(r0[c], r1[c]), __hmax2(r2[c], r3[c]));
        dst[c] = v;
    }
}

// ---------------- fp16 tensor-core GEMM ----------------
// C[M,N] = alpha * A[M,K] . B[N,K]^T (+bias);  K contiguous, fp16 in/out.
// CTA tile 128x128, 4 warps (2x2), warp tile 64x64, BK=64 halves.
// 3-stage cp.async, 2 CTAs/SM.
// BIASM: bias indexed by M (else by N when bias != null).
// EPI: 0 = plain;
//      1 = exp epilogue: C = exp(alpha*acc), atomicAdd row sums into aux[b*auxStride+m]
//      2 = rowdiv:       C = (alpha*acc+bias) * (1/aux[b*auxStride+m])
//      3 = bnstats:      C as plain, atomicAdd per-N-column sum/sumsq into aux/aux2
#define NSTG 3
#define HSM_A_STAGE 16384
#define HSM_B_OFF   (NSTG * HSM_A_STAGE)
#define HSM_B_STAGE 16384
#define HSM_TOTAL   (NSTG * (HSM_A_STAGE + HSM_B_STAGE))   // 98304

template <int BIASM, int EPI>
__global__ void __launch_bounds__(128, 2) hgemm(
    const __half* __restrict__ A, const __half* __restrict__ Bp,
    __half* __restrict__ C, const float* __restrict__ bias,
    float* aux, float* aux2, int auxStride,
    int M, int N, int K, size_t sA, size_t sB, size_t sC, float alpha)
{
    extern __shared__ char smem[];
    uint32_t sb;
    asm("{ .reg .u64 t; cvta.to.shared.u64 t, %1; cvt.u32.u64 %0, t; }" : "=r"(sb) : "l"(smem));

    const int b = blockIdx.z;
    A  += (size_t)b * sA;
    Bp += (size_t)b * sB;

    const int m0 = blockIdx.y * 128;
    const int n0 = blockIdx.x * 128;
    const int tid = threadIdx.x;
    const int wid = tid >> 5;
    const int lane = tid & 31;
    const int wm = wid & 1;          // 2 warps along M -> 64 rows each
    const int wn = wid >> 1;         // 2 warps along N -> 64 cols each

    const int g = lane >> 3;
    const int rr = lane & 7;
    const int row_off = ((g & 1) << 3) + rr;
    const int chunk_g = g >> 1;

    float acc[4][8][4];
#pragma unroll
    for (int mi = 0; mi < 4; mi++)
#pragma unroll
        for (int ni = 0; ni < 8; ni++)
#pragma unroll
            for (int v = 0; v < 4; v++) acc[mi][ni][v] = 0.f;

    const int NT = K / 64;

    auto prefetch = [&](int it, int buf) {
        const int k0 = it * 64;
        uint32_t sAb = sb + buf * HSM_A_STAGE;
        uint32_t sBb = sb + HSM_B_OFF + buf * HSM_B_STAGE;
#pragma unroll
        for (int i = 0; i < 8; i++) {
            int l = tid + i * 128;
            int r = l >> 3, c = l & 7;
            cp16(sAb + r * 128 + ((c ^ (r & 7)) << 4),
                 A + (size_t)(m0 + r) * K + k0 + c * 8);
        }
#pragma unroll
        for (int i = 0; i < 8; i++) {
            int l = tid + i * 128;
            int r = l >> 3, c = l & 7;
            cp16(sBb + r * 128 + ((c ^ (r & 7)) << 4),
                 Bp + (size_t)(n0 + r) * K + k0 + c * 8);
        }
    };

#pragma unroll
    for (int p = 0; p < NSTG - 1; p++) {
        if (p < NT) prefetch(p, p);
        asm volatile("cp.async.commit_group;\n" ::);
    }

    int buf = 0;
    for (int it = 0; it < NT; it++) {
        if (it + NSTG - 1 < NT) {
            int pb = it + NSTG - 1;
            prefetch(pb, pb % NSTG);
        }
        asm volatile("cp.async.commit_group;\n" ::);
        asm volatile("cp.async.wait_group %0;\n" :: "n"(NSTG - 1));
        __syncthreads();

        const uint32_t sA = sb + buf * HSM_A_STAGE;
        const uint32_t sB = sb + HSM_B_OFF + buf * HSM_B_STAGE;

#pragma unroll
        for (int kk = 0; kk < 4; kk++) {
            uint32_t af[4][4], bf[4][4];
#pragma unroll
            for (int mi = 0; mi < 4; mi++) {
                int m_loc = wm * 64 + mi * 16 + row_off;
                int chunk = kk * 2 + chunk_g;
                uint32_t addr = sA + m_loc * 128 + ((chunk ^ (m_loc & 7)) << 4);
                asm volatile("ldmatrix.sync.aligned.m8n8.x4.shared.b16 {%0,%1,%2,%3}, [%4];"
                             : "=r"(af[mi][0]), "=r"(af[mi][1]),
                               "=r"(af[mi][2]), "=r"(af[mi][3])
                             : "r"(addr));
            }
#pragma unroll
            for (int np = 0; np < 4; np++) {
                int n_loc = wn * 64 + np * 16 + row_off;
                int chunk = kk * 2 + chunk_g;
                uint32_t addr = sB + n_loc * 128 + ((chunk ^ (n_loc & 7)) << 4);
                asm volatile("ldmatrix.sync.aligned.m8n8.x4.shared.b16 {%0,%1,%2,%3}, [%4];"
                             : "=r"(bf[np][0]), "=r"(bf[np][1]),
                               "=r"(bf[np][2]), "=r"(bf[np][3])
                             : "r"(addr));
            }
#pragma unroll
            for (int mi = 0; mi < 4; mi++)
#pragma unroll
                for (int ni = 0; ni < 8; ni++) {
                    uint32_t b0 = bf[ni >> 1][(ni & 1)];
                    uint32_t b1 = bf[ni >> 1][2 + (ni & 1)];
                    asm volatile(
                        "mma.sync.aligned.m16n8k16.row.col.f32.f16.f16.f32 "
                        "{%0,%1,%2,%3}, {%4,%5,%6,%7}, {%8,%9}, {%0,%1,%2,%3};\n"
                        : "+f"(acc[mi][ni][0]), "+f"(acc[mi][ni][1]),
                          "+f"(acc[mi][ni][2]), "+f"(acc[mi][ni][3])
                        : "r"(af[mi][0]), "r"(af[mi][1]), "r"(af[mi][2]), "r"(af[mi][3]),
                          "r"(b0), "r"(b1));
                }
        }
        __syncthreads();
        if (++buf == NSTG) buf = 0;
    }

    // ---- epilogue ----
    C += (size_t)b * sC;
    float csum[8][2], csq[8][2];
    if (EPI == 3) {
#pragma unroll
        for (int ni = 0; ni < 8; ni++) {
            csum[ni][0] = csum[ni][1] = 0.f;
            csq[ni][0] = csq[ni][1] = 0.f;
        }
    }
#pragma unroll
    for (int mi = 0; mi < 4; mi++) {
        int m = m0 + wm * 64 + mi * 16 + (lane >> 2);
        float bm0 = 0.f, bm1 = 0.f;
        if (BIASM && bias) { bm0 = bias[m]; bm1 = bias[m + 8]; }
        float inv0 = 1.f, inv1 = 1.f;
        if (EPI == 2) {
            inv0 = 1.f / aux[(size_t)b * auxStride + m];
            inv1 = 1.f / aux[(size_t)b * auxStride + m + 8];
        }
        float rs0 = 0.f, rs1 = 0.f;
#pragma unroll
        for (int ni = 0; ni < 8; ni++) {
            int n = n0 + wn * 64 + ni * 8 + (lane & 3) * 2;
            float v0 = acc[mi][ni][0] * alpha;
            float v1 = acc[mi][ni][1] * alpha;
            float v2 = acc[mi][ni][2] * alpha;
            float v3 = acc[mi][ni][3] * alpha;
            if (BIASM) {
                v0 += bm0; v1 += bm0; v2 += bm1; v3 += bm1;
            } else if (bias) {
                float bn0 = bias[n], bn1 = bias[n + 1];
                v0 += bn0; v1 += bn1; v2 += bn0; v3 += bn1;
            }
            if (EPI == 1) {
                v0 = __expf(v0); v1 = __expf(v1);
                v2 = __expf(v2); v3 = __expf(v3);
                rs0 += v0 + v1;
                rs1 += v2 + v3;
            }
            if (EPI == 2) {
                v0 *= inv0; v1 *= inv0; v2 *= inv1; v3 *= inv1;
            }
            if (EPI == 3) {
                csum[ni][0] += v0 + v2;  csum[ni][1] += v1 + v3;
                csq[ni][0] += v0 * v0 + v2 * v2;
                csq[ni][1] += v1 * v1 + v3 * v3;
            }
            *(__half2*)&C[(size_t)m * N + n] = __floats2half2_rn(v0, v1);
            *(__half2*)&C[(size_t)(m + 8) * N + n] = __floats2half2_rn(v2, v3);
        }
        if (EPI == 1) {
            rs0 += __shfl_xor_sync(0xffffffffu, rs0, 1);
            rs0 += __shfl_xor_sync(0xffffffffu, rs0, 2);
            rs1 += __shfl_xor_sync(0xffffffffu, rs1, 1);
            rs1 += __shfl_xor_sync(0xffffffffu, rs1, 2);
            if ((lane & 3) == 0) {
                atomicAdd(&aux[(size_t)b * auxStride + m], rs0);
                atomicAdd(&aux[(size_t)b * auxStride + m + 8], rs1);
            }
        }
    }
    if (EPI == 3) {
#pragma unroll
        for (int ni = 0; ni < 8; ni++) {
#pragma unroll
            for (int h = 0; h < 2; h++) {
                float s = csum[ni][h], q = csq[ni][h];
                s += __shfl_xor_sync(0xffffffffu, s, 4);
                s += __shfl_xor_sync(0xffffffffu, s, 8);
                s += __shfl_xor_sync(0xffffffffu, s, 16);
                q += __shfl_xor_sync(0xffffffffu, q, 4);
                q += __shfl_xor_sync(0xffffffffu, q, 8);
                q += __shfl_xor_sync(0xffffffffu, q, 16);
                if ((lane >> 2) == 0) {
                    int n = n0 + wn * 64 + ni * 8 + (lane & 3) * 2 + h;
                    atomicAdd(&aux[n], s);
                    atomicAdd(&aux2[n], q);
                }
            }
        }
    }
}

// ---------------- BN finalize from fused accumulators ----------------
__global__ void bn_final_kernel() {
    int c = blockIdx.x * 256 + threadIdx.x;
    const float inv_n = 1.0f / (float)(BATCH * HW);
    float mean = d_bnsum[c] * inv_n;
    float var = d_bnsq[c] * inv_n - mean * mean;
    d_mean[c] = mean;
    d_rstd[c] = rsqrtf(var + 1e-5f);
}

// ---------------- final: out[b][c][hw] = x + norm(zTh[b][hw][c]) ----------------
__global__ void final_kernel(const float* __restrict__ x,
                             const float* __restrict__ gamma,
                             const float* __restrict__ beta,
                             float* __restrict__ out) {
    __shared__ float s[32][33];
    int b = blockIdx.z;
    int hw0 = blockIdx.x * 32, c0 = blockIdx.y * 32;
    int tx = threadIdx.x & 31, ty = threadIdx.x >> 5;
#pragma unroll
    for (int k = 0; k < 4; k++)
        s[ty + 8 * k][tx] =
            __half2float(d_zTh[((size_t)(b * HW) + hw0 + ty + 8 * k) * CIN + c0 + tx]);
    __syncthreads();
#pragma unroll
    for (int k = 0; k < 4; k++) {
        int c = c0 + ty + 8 * k;
        size_t o = ((size_t)(b * CIN) + c) * HW + hw0 + tx;
        float sc = d_rstd[c] * gamma[c];
        float off = beta[c] - d_mean[c] * sc;
        out[o] = x[o] + s[tx][ty + 8 * k] * sc + off;
    }
}

extern "C" void kernel_launch(void* const* d_in, const int* in_sizes, int n_in,
                              void* d_out, int out_size) {
    const float* x       = (const float*)d_in[0];
    const float* theta_b = (const float*)d_in[2];
    const float* phi_b   = (const float*)d_in[4];
    const float* g_b     = (const float*)d_in[6];
    const float* wz_b    = (const float*)d_in[8];
    const float* gamma   = (const float*)d_in[9];
    const float* beta    = (const float*)d_in[10];
    float* out = (float*)d_out;

    __half *xTh, *xpTh, *thetaTh, *phiTh, *Gh, *attnh, *yTh, *zTh, *w4h;
    float *rowsum, *bnsum, *bnsq;
    cudaGetSymbolAddress((void**)&xTh, d_xTh);
    cudaGetSymbolAddress((void**)&xpTh, d_xpTh);
    cudaGetSymbolAddress((void**)&thetaTh, d_thetaTh);
    cudaGetSymbolAddress((void**)&phiTh, d_phiTh);
    cudaGetSymbolAddress((void**)&Gh, d_Gh);
    cudaGetSymbolAddress((void**)&attnh, d_attnh);
    cudaGetSymbolAddress((void**)&yTh, d_yTh);
    cudaGetSymbolAddress((void**)&zTh, d_zTh);
    cudaGetSymbolAddress((void**)&w4h, d_w4h);
    cudaGetSymbolAddress((void**)&rowsum, d_rowsum);
    cudaGetSymbolAddress((void**)&bnsum, d_bnsum);
    cudaGetSymbolAddress((void**)&bnsq, d_bnsq);

    cudaFuncSetAttribute(hgemm<0, 0>, cudaFuncAttributeMaxDynamicSharedMemorySize, HSM_TOTAL);
    cudaFuncSetAttribute(hgemm<1, 0>, cudaFuncAttributeMaxDynamicSharedMemorySize, HSM_TOTAL);
    cudaFuncSetAttribute(hgemm<0, 1>, cudaFuncAttributeMaxDynamicSharedMemorySize, HSM_TOTAL);
    cudaFuncSetAttribute(hgemm<0, 2>, cudaFuncAttributeMaxDynamicSharedMemorySize, HSM_TOTAL);
    cudaFuncSetAttribute(hgemm<0, 3>, cudaFuncAttributeMaxDynamicSharedMemorySize, HSM_TOTAL);

    // 0. prep
    zero_kernel<<<(BATCH * HW + 255) / 256, 256>>>();
    round_weights_kernel<<<(WSZ + 255) / 256, 256>>>(
        (const float*)d_in[1], (const float*)d_in[3], (const float*)d_in[5], (const float*)d_in[7]);
    transpose_x_kernel<<<dim3(HW / 32, CIN / 32, BATCH), 256>>>(x);
    maxpool_t_kernel<<<dim3(HWP, BATCH), 256>>>();

    // 1. thetaT[HW,CI] = xT . theta_w^T + theta_b (per N)
    hgemm<0, 0><<<dim3(CI / 128, HW / 128, BATCH), 128, HSM_TOTAL>>>(
        xTh, w4h + 0 * WSZ, thetaTh, theta_b, nullptr, nullptr, 0,
        HW, CI, CIN, (size_t)HW * CIN, 0, (size_t)HW * CI, 1.0f);

    // 2. phiT[HWP,CI] = xpT . phi_w^T + phi_b (per N)
    hgemm<0, 0><<<dim3(CI / 128, HWP / 128, BATCH), 128, HSM_TOTAL>>>(
        xpTh, w4h + 1 * WSZ, phiTh, phi_b, nullptr, nullptr, 0,
        HWP, CI, CIN, (size_t)HWP * CIN, 0, (size_t)HWP * CI, 1.0f);

    // 3. G[CI,HWP] = g_w . xpT^T + g_b (per M)
    hgemm<1, 0><<<dim3(HWP / 128, CI / 128, BATCH), 128, HSM_TOTAL>>>(
        w4h + 2 * WSZ, xpTh, Gh, g_b, nullptr, nullptr, 0,
        CI, HWP, CIN, 0, (size_t)HWP * CIN, (size_t)CI * HWP, 1.0f);

    // 4. attnE[HW,HWP] = exp(thetaT . phiT^T * scale); rowsum accumulated
    const float scale = 1.0f / sqrtf((float)CI);
    hgemm<0, 1><<<dim3(HWP / 128, HW / 128, BATCH), 128, HSM_TOTAL>>>(
        thetaTh, phiTh, attnh, nullptr, rowsum, nullptr, HW,
        HW, HWP, CI, (size_t)HW * CI, (size_t)HWP * CI, (size_t)HW * HWP, scale);

    // 5. yT[HW,CI] = (attnE . G^T) / rowsum[m]
    hgemm<0, 2><<<dim3(CI / 128, HW / 128, BATCH), 128, HSM_TOTAL>>>(
        attnh, Gh, yTh, nullptr, rowsum, nullptr, HW,
        HW, CI, HWP, (size_t)HW * HWP, (size_t)CI * HWP, (size_t)HW * CI, 1.0f);

    // 6. zTh[HW,CIN] = yT . wz_w^T + wz_b (per N); BN sums accumulated
    hgemm<0, 3><<<dim3(CIN / 128, HW / 128, BATCH), 128, HSM_TOTAL>>>(
        yTh, w4h + 3 * WSZ, zTh, wz_b, bnsum, bnsq, 0,
        HW, CIN, CI, (size_t)HW * CI, 0, (size_t)HW * CIN, 1.0f);

    // 7. BN finalize
    bn_final_kernel<<<CIN / 256, 256>>>();

    // 8. out = x + gamma*(zTh-mean)*rstd + beta (transpose back)
    final_kernel<<<dim3(HW / 32, CIN / 32, BATCH), 256>>>(x, gamma, beta, out);
}

// round 14
// speedup vs baseline: 1.6054x; 1.0188x over previous
#include <cuda_runtime.h>
#include <cuda_fp16.h>
#include <math.h>
#include <stdint.h>

#define BATCH 8
#define CIN 1024
#define CI 512
#define HW 4096     // 64*64
#define HWP 1024    // 32*32
#define WSZ 524288  // each weight matrix is 512*1024 elements

// ---- scratch (static device globals; no runtime allocation) ----
__device__ __half d_xTh[(size_t)BATCH * HW * CIN];
__device__ __half d_xpTh[(size_t)BATCH * HWP * CIN];
__device__ __half d_thetaTh[(size_t)BATCH * HW * CI];
__device__ __half d_phiTh[(size_t)BATCH * HWP * CI];
__device__ __half d_Gh[(size_t)BATCH * CI * HWP];      // [CI][HWP] per batch
__device__ __half d_attnh[(size_t)BATCH * HW * HWP];   // exp(scores), unnormalized
__device__ __half d_yTh[(size_t)BATCH * HW * CI];
__device__ __half d_zTh[(size_t)BATCH * HW * CIN];     // fp16 z
__device__ __half d_w4h[4 * WSZ];
__device__ float d_rowsum[(size_t)BATCH * HW];
__device__ float d_bnsum[CIN];
__device__ float d_bnsq[CIN];

__device__ __forceinline__ void cp16(uint32_t dst, const void* src) {
    asm volatile("cp.async.cg.shared.global [%0], [%1], 16;\n" :: "r"(dst), "l"(src));
}

// ---------------- prep: round weights to fp16 + zero accumulators ----------------
__global__ void round_weights_kernel(const float* __restrict__ w0, const float* __restrict__ w1,
                                     const float* __restrict__ w2, const float* __restrict__ w3) {
    int i = blockIdx.x * blockDim.x + threadIdx.x;
    if (i >= WSZ) return;
    d_w4h[0 * WSZ + i] = __float2half_rn(w0[i]);
    d_w4h[1 * WSZ + i] = __float2half_rn(w1[i]);
    d_w4h[2 * WSZ + i] = __float2half_rn(w2[i]);
    d_w4h[3 * WSZ + i] = __float2half_rn(w3[i]);
    if (i < BATCH * HW) d_rowsum[i] = 0.f;
    if (i < CIN) { d_bnsum[i] = 0.f; d_bnsq[i] = 0.f; }
}

// Fused transpose + 2x2 maxpool.
// Block covers 2 spatial rows (hw in [pi*128, pi*128+128)) x 32 channels.
// Emits xTh[b][hw][c] (fp16 transposed) and xpTh[b][p][c] (pooled).
__global__ void transpose_pool_kernel(const float* __restrict__ x) {
    __shared__ float s[32][129];
    int b = blockIdx.z;
    int pi = blockIdx.x;       // pooled row 0..31
    int c0 = blockIdx.y * 32;
    int tid = threadIdx.x;     // 256
#pragma unroll
    for (int l = 0; l < 16; l++) {
        int idx = tid + l * 256;
        int c = idx >> 7, e = idx & 127;
        s[c][e] = x[((size_t)(b * CIN) + c0 + c) * HW + pi * 128 + e];
    }
    __syncthreads();
    // transposed fp16 write: hw = pi*128 + e
#pragma unroll
    for (int l = 0; l < 16; l++) {
        int o = tid + l * 256;
        int e = o >> 5, c = o & 31;
        d_xTh[((size_t)(b * HW) + pi * 128 + e) * CIN + c0 + c] = __float2half_rn(s[c][e]);
    }
    // pooled write: p = pi*32 + pj
#pragma unroll
    for (int l = 0; l < 4; l++) {
        int o = tid + l * 256;
        int p = o >> 5, c = o & 31;
        float v = fmaxf(fmaxf(s[c][2 * p], s[c][2 * p + 1]),
                        fmaxf(s[c][64 + 2 * p], s[c][64 + 2 * p + 1]));
        d_xpTh[((size_t)(b * HWP) + pi * 32 + p) * CIN + c0 + c] = __float2half_rn(v);
    }
}

// ---------------- fp16 tensor-core GEMM ----------------
// C[M,N] = alpha * A[M,K] . B[N,K]^T (+bias);  K contiguous, fp16 in/out.
// CTA tile 128x128, 4 warps (2x2), warp tile 64x64, BK=64 halves.
// 3-stage cp.async, 2 CTAs/SM.
// BIASM: bias indexed by M (else by N when bias != null).
// EPI: 0 = plain;
//      1 = exp epilogue: C = exp(alpha*acc), atomicAdd row sums into aux[b*auxStride+m]
//      2 = rowdiv:       C = (alpha*acc+bias) * (1/aux[b*auxStride+m])
//      3 = bnstats:      C as plain, atomicAdd per-N-column sum/sumsq into aux/aux2
#define NSTG 3
#define HSM_A_STAGE 16384
#define HSM_B_OFF   (NSTG * HSM_A_STAGE)
#define HSM_B_STAGE 16384
#define HSM_TOTAL   (NSTG * (HSM_A_STAGE + HSM_B_STAGE))   // 98304

template <int BIASM, int EPI>
__global__ void __launch_bounds__(128, 2) hgemm(
    const __half* __restrict__ A, const __half* __restrict__ Bp,
    __half* __restrict__ C, const float* __restrict__ bias,
    float* aux, float* aux2, int auxStride,
    int M, int N, int K, size_t sA, size_t sB, size_t sC, float alpha)
{
    extern __shared__ char smem[];
    uint32_t sb;
    asm("{ .reg .u64 t; cvta.to.shared.u64 t, %1; cvt.u32.u64 %0, t; }" : "=r"(sb) : "l"(smem));

    const int b = blockIdx.z;
    A  += (size_t)b * sA;
    Bp += (size_t)b * sB;

    const int m0 = blockIdx.y * 128;
    const int n0 = blockIdx.x * 128;
    const int tid = threadIdx.x;
    const int wid = tid >> 5;
    const int lane = tid & 31;
    const int wm = wid & 1;          // 2 warps along M -> 64 rows each
    const int wn = wid >> 1;         // 2 warps along N -> 64 cols each

    const int g = lane >> 3;
    const int rr = lane & 7;
    const int row_off = ((g & 1) << 3) + rr;
    const int chunk_g = g >> 1;

    float acc[4][8][4];
#pragma unroll
    for (int mi = 0; mi < 4; mi++)
#pragma unroll
        for (int ni = 0; ni < 8; ni++)
#pragma unroll
            for (int v = 0; v < 4; v++) acc[mi][ni][v] = 0.f;

    const int NT = K / 64;

    auto prefetch = [&](int it, int buf) {
        const int k0 = it * 64;
        uint32_t sAb = sb + buf * HSM_A_STAGE;
        uint32_t sBb = sb + HSM_B_OFF + buf * HSM_B_STAGE;
#pragma unroll
        for (int i = 0; i < 8; i++) {
            int l = tid + i * 128;
            int r = l >> 3, c = l & 7;
            cp16(sAb + r * 128 + ((c ^ (r & 7)) << 4),
                 A + (size_t)(m0 + r) * K + k0 + c * 8);
        }
#pragma unroll
        for (int i = 0; i < 8; i++) {
            int l = tid + i * 128;
            int r = l >> 3, c = l & 7;
            cp16(sBb + r * 128 + ((c ^ (r & 7)) << 4),
                 Bp + (size_t)(n0 + r) * K + k0 + c * 8);
        }
    };

#pragma unroll
    for (int p = 0; p < NSTG - 1; p++) {
        if (p < NT) prefetch(p, p);
        asm volatile("cp.async.commit_group;\n" ::);
    }

    int buf = 0;
    for (int it = 0; it < NT; it++) {
        if (it + NSTG - 1 < NT) {
            int pb = it + NSTG - 1;
            prefetch(pb, pb % NSTG);
        }
        asm volatile("cp.async.commit_group;\n" ::);
        asm volatile("cp.async.wait_group %0;\n" :: "n"(NSTG - 1));
        __syncthreads();

        const uint32_t sA = sb + buf * HSM_A_STAGE;
        const uint32_t sB = sb + HSM_B_OFF + buf * HSM_B_STAGE;

#pragma unroll
        for (int kk = 0; kk < 4; kk++) {
            uint32_t af[4][4], bf[4][4];
#pragma unroll
            for (int mi = 0; mi < 4; mi++) {
                int m_loc = wm * 64 + mi * 16 + row_off;
                int chunk = kk * 2 + chunk_g;
                uint32_t addr = sA + m_loc * 128 + ((chunk ^ (m_loc & 7)) << 4);
                asm volatile("ldmatrix.sync.aligned.m8n8.x4.shared.b16 {%0,%1,%2,%3}, [%4];"
                             : "=r"(af[mi][0]), "=r"(af[mi][1]),
                               "=r"(af[mi][2]), "=r"(af[mi][3])
                             : "r"(addr));
            }
#pragma unroll
            for (int np = 0; np < 4; np++) {
                int n_loc = wn * 64 + np * 16 + row_off;
                int chunk = kk * 2 + chunk_g;
                uint32_t addr = sB + n_loc * 128 + ((chunk ^ (n_loc & 7)) << 4);
                asm volatile("ldmatrix.sync.aligned.m8n8.x4.shared.b16 {%0,%1,%2,%3}, [%4];"
                             : "=r"(bf[np][0]), "=r"(bf[np][1]),
                               "=r"(bf[np][2]), "=r"(bf[np][3])
                             : "r"(addr));
            }
#pragma unroll
            for (int mi = 0; mi < 4; mi++)
#pragma unroll
                for (int ni = 0; ni < 8; ni++) {
                    uint32_t b0 = bf[ni >> 1][(ni & 1)];
                    uint32_t b1 = bf[ni >> 1][2 + (ni & 1)];
                    asm volatile(
                        "mma.sync.aligned.m16n8k16.row.col.f32.f16.f16.f32 "
                        "{%0,%1,%2,%3}, {%4,%5,%6,%7}, {%8,%9}, {%0,%1,%2,%3};\n"
                        : "+f"(acc[mi][ni][0]), "+f"(acc[mi][ni][1]),
                          "+f"(acc[mi][ni][2]), "+f"(acc[mi][ni][3])
                        : "r"(af[mi][0]), "r"(af[mi][1]), "r"(af[mi][2]), "r"(af[mi][3]),
                          "r"(b0), "r"(b1));
                }
        }
        __syncthreads();
        if (++buf == NSTG) buf = 0;
    }

    // ---- epilogue ----
    C += (size_t)b * sC;
    float csum[8][2], csq[8][2];
    if (EPI == 3) {
#pragma unroll
        for (int ni = 0; ni < 8; ni++) {
            csum[ni][0] = csum[ni][1] = 0.f;
            csq[ni][0] = csq[ni][1] = 0.f;
        }
    }
#pragma unroll
    for (int mi = 0; mi < 4; mi++) {
        int m = m0 + wm * 64 + mi * 16 + (lane >> 2);
        float bm0 = 0.f, bm1 = 0.f;
        if (BIASM && bias) { bm0 = bias[m]; bm1 = bias[m + 8]; }
        float inv0 = 1.f, inv1 = 1.f;
        if (EPI == 2) {
            inv0 = 1.f / aux[(size_t)b * auxStride + m];
            inv1 = 1.f / aux[(size_t)b * auxStride + m + 8];
        }
        float rs0 = 0.f, rs1 = 0.f;
#pragma unroll
        for (int ni = 0; ni < 8; ni++) {
            int n = n0 + wn * 64 + ni * 8 + (lane & 3) * 2;
            float v0 = acc[mi][ni][0] * alpha;
            float v1 = acc[mi][ni][1] * alpha;
            float v2 = acc[mi][ni][2] * alpha;
            float v3 = acc[mi][ni][3] * alpha;
            if (BIASM) {
                v0 += bm0; v1 += bm0; v2 += bm1; v3 += bm1;
            } else if (bias) {
                float bn0 = bias[n], bn1 = bias[n + 1];
                v0 += bn0; v1 += bn1; v2 += bn0; v3 += bn1;
            }
            if (EPI == 1) {
                v0 = __expf(v0); v1 = __expf(v1);
                v2 = __expf(v2); v3 = __expf(v3);
                rs0 += v0 + v1;
                rs1 += v2 + v3;
            }
            if (EPI == 2) {
                v0 *= inv0; v1 *= inv0; v2 *= inv1; v3 *= inv1;
            }
            if (EPI == 3) {
                csum[ni][0] += v0 + v2;  csum[ni][1] += v1 + v3;
                csq[ni][0] += v0 * v0 + v2 * v2;
                csq[ni][1] += v1 * v1 + v3 * v3;
            }
            *(__half2*)&C[(size_t)m * N + n] = __floats2half2_rn(v0, v1);
            *(__half2*)&C[(size_t)(m + 8) * N + n] = __floats2half2_rn(v2, v3);
        }
        if (EPI == 1) {
            rs0 += __shfl_xor_sync(0xffffffffu, rs0, 1);
            rs0 += __shfl_xor_sync(0xffffffffu, rs0, 2);
            rs1 += __shfl_xor_sync(0xffffffffu, rs1, 1);
            rs1 += __shfl_xor_sync(0xffffffffu, rs1, 2);
            if ((lane & 3) == 0) {
                atomicAdd(&aux[(size_t)b * auxStride + m], rs0);
                atomicAdd(&aux[(size_t)b * auxStride + m + 8], rs1);
            }
        }
    }
    if (EPI == 3) {
#pragma unroll
        for (int ni = 0; ni < 8; ni++) {
#pragma unroll
            for (int h = 0; h < 2; h++) {
                float s = csum[ni][h], q = csq[ni][h];
                s += __shfl_xor_sync(0xffffffffu, s, 4);
                s += __shfl_xor_sync(0xffffffffu, s, 8);
                s += __shfl_xor_sync(0xffffffffu, s, 16);
                q += __shfl_xor_sync(0xffffffffu, q, 4);
                q += __shfl_xor_sync(0xffffffffu, q, 8);
                q += __shfl_xor_sync(0xffffffffu, q, 16);
                if ((lane >> 2) == 0) {
                    int n = n0 + wn * 64 + ni * 8 + (lane & 3) * 2 + h;
                    atomicAdd(&aux[n], s);
                    atomicAdd(&aux2[n], q);
                }
            }
        }
    }
}

// ---------------- final: out = x + gamma*(z-mean)*rstd + beta (BN inline) ----------------
__global__ void final_kernel(const float* __restrict__ x,
                             const float* __restrict__ gamma,
                             const float* __restrict__ beta,
                             float* __restrict__ out) {
    __shared__ float s[32][33];
    int b = blockIdx.z;
    int hw0 = blockIdx.x * 32, c0 = blockIdx.y * 32;
    int tx = threadIdx.x & 31, ty = threadIdx.x >> 5;
#pragma unroll
    for (int k = 0; k < 4; k++)
        s[ty + 8 * k][tx] =
            __half2float(d_zTh[((size_t)(b * HW) + hw0 + ty + 8 * k) * CIN + c0 + tx]);
    __syncthreads();
    const float inv_n = 1.0f / (float)(BATCH * HW);
#pragma unroll
    for (int k = 0; k < 4; k++) {
        int c = c0 + ty + 8 * k;
        float mean = d_bnsum[c] * inv_n;
        float var = d_bnsq[c] * inv_n - mean * mean;
        float rstd = rsqrtf(var + 1e-5f);
        size_t o = ((size_t)(b * CIN) + c) * HW + hw0 + tx;
        float sc = rstd * gamma[c];
        float off = beta[c] - mean * sc;
        out[o] = x[o] + s[tx][ty + 8 * k] * sc + off;
    }
}

extern "C" void kernel_launch(void* const* d_in, const int* in_sizes, int n_in,
                              void* d_out, int out_size) {
    const float* x       = (const float*)d_in[0];
    const float* theta_b = (const float*)d_in[2];
    const float* phi_b   = (const float*)d_in[4];
    const float* g_b     = (const float*)d_in[6];
    const float* wz_b    = (const float*)d_in[8];
    const float* gamma   = (const float*)d_in[9];
    const float* beta    = (const float*)d_in[10];
    float* out = (float*)d_out;

    __half *xTh, *xpTh, *thetaTh, *phiTh, *Gh, *attnh, *yTh, *zTh, *w4h;
    float *rowsum, *bnsum, *bnsq;
    cudaGetSymbolAddress((void**)&xTh, d_xTh);
    cudaGetSymbolAddress((void**)&xpTh, d_xpTh);
    cudaGetSymbolAddress((void**)&thetaTh, d_thetaTh);
    cudaGetSymbolAddress((void**)&phiTh, d_phiTh);
    cudaGetSymbolAddress((void**)&Gh, d_Gh);
    cudaGetSymbolAddress((void**)&attnh, d_attnh);
    cudaGetSymbolAddress((void**)&yTh, d_yTh);
    cudaGetSymbolAddress((void**)&zTh, d_zTh);
    cudaGetSymbolAddress((void**)&w4h, d_w4h);
    cudaGetSymbolAddress((void**)&rowsum, d_rowsum);
    cudaGetSymbolAddress((void**)&bnsum, d_bnsum);
    cudaGetSymbolAddress((void**)&bnsq, d_bnsq);

    cudaFuncSetAttribute(hgemm<0, 0>, cudaFuncAttributeMaxDynamicSharedMemorySize, HSM_TOTAL);
    cudaFuncSetAttribute(hgemm<1, 0>, cudaFuncAttributeMaxDynamicSharedMemorySize, HSM_TOTAL);
    cudaFuncSetAttribute(hgemm<0, 1>, cudaFuncAttributeMaxDynamicSharedMemorySize, HSM_TOTAL);
    cudaFuncSetAttribute(hgemm<0, 2>, cudaFuncAttributeMaxDynamicSharedMemorySize, HSM_TOTAL);
    cudaFuncSetAttribute(hgemm<0, 3>, cudaFuncAttributeMaxDynamicSharedMemorySize, HSM_TOTAL);

    // 0. prep: round weights + zero accumulators; fused transpose+pool
    round_weights_kernel<<<(WSZ + 255) / 256, 256>>>(
        (const float*)d_in[1], (const float*)d_in[3], (const float*)d_in[5], (const float*)d_in[7]);
    transpose_pool_kernel<<<dim3(32, CIN / 32, BATCH), 256>>>(x);

    // 1. thetaT[HW,CI] = xT . theta_w^T + theta_b (per N)
    hgemm<0, 0><<<dim3(CI / 128, HW / 128, BATCH), 128, HSM_TOTAL>>>(
        xTh, w4h + 0 * WSZ, thetaTh, theta_b, nullptr, nullptr, 0,
        HW, CI, CIN, (size_t)HW * CIN, 0, (size_t)HW * CI, 1.0f);

    // 2. phiT[HWP,CI] = xpT . phi_w^T + phi_b (per N)
    hgemm<0, 0><<<dim3(CI / 128, HWP / 128, BATCH), 128, HSM_TOTAL>>>(
        xpTh, w4h + 1 * WSZ, phiTh, phi_b, nullptr, nullptr, 0,
        HWP, CI, CIN, (size_t)HWP * CIN, 0, (size_t)HWP * CI, 1.0f);

    // 3. G[CI,HWP] = g_w . xpT^T + g_b (per M)
    hgemm<1, 0><<<dim3(HWP / 128, CI / 128, BATCH), 128, HSM_TOTAL>>>(
        w4h + 2 * WSZ, xpTh, Gh, g_b, nullptr, nullptr, 0,
        CI, HWP, CIN, 0, (size_t)HWP * CIN, (size_t)CI * HWP, 1.0f);

    // 4. attnE[HW,HWP] = exp(thetaT . phiT^T * scale); rowsum accumulated
    const float scale = 1.0f / sqrtf((float)CI);
    hgemm<0, 1><<<dim3(HWP / 128, HW / 128, BATCH), 128, HSM_TOTAL>>>(
        thetaTh, phiTh, attnh, nullptr, rowsum, nullptr, HW,
        HW, HWP, CI, (size_t)HW * CI, (size_t)HWP * CI, (size_t)HW * HWP, scale);

    // 5. yT[HW,CI] = (attnE . G^T) / rowsum[m]
    hgemm<0, 2><<<dim3(CI / 128, HW / 128, BATCH), 128, HSM_TOTAL>>>(
        attnh, Gh, yTh, nullptr, rowsum, nullptr, HW,
        HW, CI, HWP, (size_t)HW * HWP, (size_t)CI * HWP, (size_t)HW * CI, 1.0f);

    // 6. zTh[HW,CIN] = yT . wz_w^T + wz_b (per N); BN sums accumulated
    hgemm<0, 3><<<dim3(CIN / 128, HW / 128, BATCH), 128, HSM_TOTAL>>>(
        yTh, w4h + 3 * WSZ, zTh, wz_b, bnsum, bnsq, 0,
        HW, CIN, CI, (size_t)HW * CI, 0, (size_t)HW * CIN, 1.0f);

    // 7. out = x + gamma*(z-mean)*rstd + beta (BN finalize inline)
    final_kernel<<<dim3(HW / 32, CIN / 32, BATCH), 256>>>(x, gamma, beta, out);
}

// round 15
// speedup vs baseline: 1.6313x; 1.0161x over previous
#include <cuda_runtime.h>
#include <cuda_fp16.h>
#include <math.h>
#include <stdint.h>

#define BATCH 8
#define CIN 1024
#define CI 512
#define HW 4096     // 64*64
#define HWP 1024    // 32*32
#define WSZ 524288  // each weight matrix is 512*1024 elements

// ---- scratch (static device globals; no runtime allocation) ----
__device__ __half d_xTh[(size_t)BATCH * HW * CIN];
__device__ __half d_xpTh[(size_t)BATCH * HWP * CIN];
__device__ __half d_thetaTh[(size_t)BATCH * HW * CI];
__device__ __half d_phiTh[(size_t)BATCH * HWP * CI];
__device__ __half d_Gh[(size_t)BATCH * CI * HWP];      // [CI][HWP] per batch
__device__ __half d_attnh[(size_t)BATCH * HW * HWP];   // exp(scores), unnormalized
__device__ __half d_yTh[(size_t)BATCH * HW * CI];
__device__ __half d_zTh[(size_t)BATCH * HW * CIN];     // fp16 z
__device__ __half d_w4h[4 * WSZ];
__device__ float d_rowsum[(size_t)BATCH * HW];
__device__ float d_bnsum[CIN];
__device__ float d_bnsq[CIN];

__device__ __forceinline__ void cp16(uint32_t dst, const void* src) {
    asm volatile("cp.async.cg.shared.global [%0], [%1], 16;\n" :: "r"(dst), "l"(src));
}

// ---------------- fused prep: transpose+pool (z<8) / round weights + zero (z==8) ----------------
__global__ void transpose_pool_kernel(const float* __restrict__ x,
                                      const float* __restrict__ w0, const float* __restrict__ w1,
                                      const float* __restrict__ w2, const float* __restrict__ w3) {
    int b = blockIdx.z;
    int tid = threadIdx.x;     // 256
    if (b == 8) {
        // weight rounding + accumulator zeroing slice
        int lin = blockIdx.y * 32 + blockIdx.x;   // 0..1023
#pragma unroll
        for (int k = 0; k < 2; k++) {
            int i = lin * 256 + tid + k * 262144;
            d_w4h[0 * WSZ + i] = __float2half_rn(w0[i]);
            d_w4h[1 * WSZ + i] = __float2half_rn(w1[i]);
            d_w4h[2 * WSZ + i] = __float2half_rn(w2[i]);
            d_w4h[3 * WSZ + i] = __float2half_rn(w3[i]);
            if (i < BATCH * HW) d_rowsum[i] = 0.f;
            if (i < CIN) { d_bnsum[i] = 0.f; d_bnsq[i] = 0.f; }
        }
        return;
    }
    __shared__ float s[32][129];
    int pi = blockIdx.x;       // pooled row 0..31
    int c0 = blockIdx.y * 32;
#pragma unroll
    for (int l = 0; l < 16; l++) {
        int idx = tid + l * 256;
        int c = idx >> 7, e = idx & 127;
        s[c][e] = x[((size_t)(b * CIN) + c0 + c) * HW + pi * 128 + e];
    }
    __syncthreads();
#pragma unroll
    for (int l = 0; l < 16; l++) {
        int o = tid + l * 256;
        int e = o >> 5, c = o & 31;
        d_xTh[((size_t)(b * HW) + pi * 128 + e) * CIN + c0 + c] = __float2half_rn(s[c][e]);
    }
#pragma unroll
    for (int l = 0; l < 4; l++) {
        int o = tid + l * 256;
        int p = o >> 5, c = o & 31;
        float v = fmaxf(fmaxf(s[c][2 * p], s[c][2 * p + 1]),
                        fmaxf(s[c][64 + 2 * p], s[c][64 + 2 * p + 1]));
        d_xpTh[((size_t)(b * HWP) + pi * 32 + p) * CIN + c0 + c] = __float2half_rn(v);
    }
}

// ---------------- fp16 tensor-core GEMM body ----------------
// C[M,N] = alpha * A[M,K] . B[N,K]^T (+bias);  K contiguous, fp16 in/out.
// CTA tile 128x128, 4 warps (2x2), warp tile 64x64, BK=64 halves.
// 3-stage cp.async, 2 CTAs/SM.
// BIASM: bias indexed by M (else by N when bias != null).
// EPI: 0 plain; 1 exp + row-sum atomics; 2 row-divide; 3 BN sum/sumsq atomics.
#define NSTG 3
#define HSM_A_STAGE 16384
#define HSM_B_OFF   (NSTG * HSM_A_STAGE)
#define HSM_B_STAGE 16384
#define HSM_TOTAL   (NSTG * (HSM_A_STAGE + HSM_B_STAGE))   // 98304

template <int BIASM, int EPI>
__device__ __forceinline__ void hgemm_body(
    const __half* __restrict__ A, const __half* __restrict__ Bp,
    __half* __restrict__ C, const float* __restrict__ bias,
    float* aux, float* aux2, int auxStride,
    int M, int N, int K, int m0, int n0, int b, uint32_t sb)
{
    const int tid = threadIdx.x;
    const int wid = tid >> 5;
    const int lane = tid & 31;
    const int wm = wid & 1;
    const int wn = wid >> 1;

    const int g = lane >> 3;
    const int rr = lane & 7;
    const int row_off = ((g & 1) << 3) + rr;
    const int chunk_g = g >> 1;

    float acc[4][8][4];
#pragma unroll
    for (int mi = 0; mi < 4; mi++)
#pragma unroll
        for (int ni = 0; ni < 8; ni++)
#pragma unroll
            for (int v = 0; v < 4; v++) acc[mi][ni][v] = 0.f;

    const int NT = K / 64;

    auto prefetch = [&](int it, int buf) {
        const int k0 = it * 64;
        uint32_t sAb = sb + buf * HSM_A_STAGE;
        uint32_t sBb = sb + HSM_B_OFF + buf * HSM_B_STAGE;
#pragma unroll
        for (int i = 0; i < 8; i++) {
            int l = tid + i * 128;
            int r = l >> 3, c = l & 7;
            cp16(sAb + r * 128 + ((c ^ (r & 7)) << 4),
                 A + (size_t)(m0 + r) * K + k0 + c * 8);
        }
#pragma unroll
        for (int i = 0; i < 8; i++) {
            int l = tid + i * 128;
            int r = l >> 3, c = l & 7;
            cp16(sBb + r * 128 + ((c ^ (r & 7)) << 4),
                 Bp + (size_t)(n0 + r) * K + k0 + c * 8);
        }
    };

#pragma unroll
    for (int p = 0; p < NSTG - 1; p++) {
        if (p < NT) prefetch(p, p);
        asm volatile("cp.async.commit_group;\n" ::);
    }

    int buf = 0;
    for (int it = 0; it < NT; it++) {
        if (it + NSTG - 1 < NT) {
            int pb = it + NSTG - 1;
            prefetch(pb, pb % NSTG);
        }
        asm volatile("cp.async.commit_group;\n" ::);
        asm volatile("cp.async.wait_group %0;\n" :: "n"(NSTG - 1));
        __syncthreads();

        const uint32_t sA = sb + buf * HSM_A_STAGE;
        const uint32_t sB = sb + HSM_B_OFF + buf * HSM_B_STAGE;

#pragma unroll
        for (int kk = 0; kk < 4; kk++) {
            uint32_t af[4][4], bf[4][4];
#pragma unroll
            for (int mi = 0; mi < 4; mi++) {
                int m_loc = wm * 64 + mi * 16 + row_off;
                int chunk = kk * 2 + chunk_g;
                uint32_t addr = sA + m_loc * 128 + ((chunk ^ (m_loc & 7)) << 4);
                asm volatile("ldmatrix.sync.aligned.m8n8.x4.shared.b16 {%0,%1,%2,%3}, [%4];"
                             : "=r"(af[mi][0]), "=r"(af[mi][1]),
                               "=r"(af[mi][2]), "=r"(af[mi][3])
                             : "r"(addr));
            }
#pragma unroll
            for (int np = 0; np < 4; np++) {
                int n_loc = wn * 64 + np * 16 + row_off;
                int chunk = kk * 2 + chunk_g;
                uint32_t addr = sB + n_loc * 128 + ((chunk ^ (n_loc & 7)) << 4);
                asm volatile("ldmatrix.sync.aligned.m8n8.x4.shared.b16 {%0,%1,%2,%3}, [%4];"
                             : "=r"(bf[np][0]), "=r"(bf[np][1]),
                               "=r"(bf[np][2]), "=r"(bf[np][3])
                             : "r"(addr));
            }
#pragma unroll
            for (int mi = 0; mi < 4; mi++)
#pragma unroll
                for (int ni = 0; ni < 8; ni++) {
                    uint32_t b0 = bf[ni >> 1][(ni & 1)];
                    uint32_t b1 = bf[ni >> 1][2 + (ni & 1)];
                    asm volatile(
                        "mma.sync.aligned.m16n8k16.row.col.f32.f16.f16.f32 "
                        "{%0,%1,%2,%3}, {%4,%5,%6,%7}, {%8,%9}, {%0,%1,%2,%3};\n"
                        : "+f"(acc[mi][ni][0]), "+f"(acc[mi][ni][1]),
                          "+f"(acc[mi][ni][2]), "+f"(acc[mi][ni][3])
                        : "r"(af[mi][0]), "r"(af[mi][1]), "r"(af[mi][2]), "r"(af[mi][3]),
                          "r"(b0), "r"(b1));
                }
        }
        __syncthreads();
        if (++buf == NSTG) buf = 0;
    }

    // ---- epilogue ----
    float csum[8][2], csq[8][2];
    if (EPI == 3) {
#pragma unroll
        for (int ni = 0; ni < 8; ni++) {
            csum[ni][0] = csum[ni][1] = 0.f;
            csq[ni][0] = csq[ni][1] = 0.f;
        }
    }
    const float alpha = (EPI == 1) ? 0.044194173824159216f /* 1/sqrt(512) */ : 1.0f;
#pragma unroll
    for (int mi = 0; mi < 4; mi++) {
        int m = m0 + wm * 64 + mi * 16 + (lane >> 2);
        float bm0 = 0.f, bm1 = 0.f;
        if (BIASM && bias) { bm0 = bias[m]; bm1 = bias[m + 8]; }
        float inv0 = 1.f, inv1 = 1.f;
        if (EPI == 2) {
            inv0 = 1.f / aux[(size_t)b * auxStride + m];
            inv1 = 1.f / aux[(size_t)b * auxStride + m + 8];
        }
        float rs0 = 0.f, rs1 = 0.f;
#pragma unroll
        for (int ni = 0; ni < 8; ni++) {
            int n = n0 + wn * 64 + ni * 8 + (lane & 3) * 2;
            float v0 = acc[mi][ni][0] * alpha;
            float v1 = acc[mi][ni][1] * alpha;
            float v2 = acc[mi][ni][2] * alpha;
            float v3 = acc[mi][ni][3] * alpha;
            if (BIASM) {
                v0 += bm0; v1 += bm0; v2 += bm1; v3 += bm1;
            } else if (bias) {
                float bn0 = bias[n], bn1 = bias[n + 1];
                v0 += bn0; v1 += bn1; v2 += bn0; v3 += bn1;
            }
            if (EPI == 1) {
                v0 = __expf(v0); v1 = __expf(v1);
                v2 = __expf(v2); v3 = __expf(v3);
                rs0 += v0 + v1;
                rs1 += v2 + v3;
            }
            if (EPI == 2) {
                v0 *= inv0; v1 *= inv0; v2 *= inv1; v3 *= inv1;
            }
            if (EPI == 3) {
                csum[ni][0] += v0 + v2;  csum[ni][1] += v1 + v3;
                csq[ni][0] += v0 * v0 + v2 * v2;
                csq[ni][1] += v1 * v1 + v3 * v3;
            }
            *(__half2*)&C[(size_t)m * N + n] = __floats2half2_rn(v0, v1);
            *(__half2*)&C[(size_t)(m + 8) * N + n] = __floats2half2_rn(v2, v3);
        }
        if (EPI == 1) {
            rs0 += __shfl_xor_sync(0xffffffffu, rs0, 1);
            rs0 += __shfl_xor_sync(0xffffffffu, rs0, 2);
            rs1 += __shfl_xor_sync(0xffffffffu, rs1, 1);
            rs1 += __shfl_xor_sync(0xffffffffu, rs1, 2);
            if ((lane & 3) == 0) {
                atomicAdd(&aux[(size_t)b * auxStride + m], rs0);
                atomicAdd(&aux[(size_t)b * auxStride + m + 8], rs1);
            }
        }
    }
    if (EPI == 3) {
#pragma unroll
        for (int ni = 0; ni < 8; ni++) {
#pragma unroll
            for (int h = 0; h < 2; h++) {
                float s = csum[ni][h], q = csq[ni][h];
                s += __shfl_xor_sync(0xffffffffu, s, 4);
                s += __shfl_xor_sync(0xffffffffu, s, 8);
                s += __shfl_xor_sync(0xffffffffu, s, 16);
                q += __shfl_xor_sync(0xffffffffu, q, 4);
                q += __shfl_xor_sync(0xffffffffu, q, 8);
                q += __shfl_xor_sync(0xffffffffu, q, 16);
                if ((lane >> 2) == 0) {
                    int n = n0 + wn * 64 + ni * 8 + (lane & 3) * 2 + h;
                    atomicAdd(&aux[n], s);
                    atomicAdd(&aux2[n], q);
                }
            }
        }
    }
}

// generic single-problem wrapper
template <int BIASM, int EPI>
__global__ void __launch_bounds__(128, 2) hgemm(
    const __half* __restrict__ A, const __half* __restrict__ Bp,
    __half* __restrict__ C, const float* __restrict__ bias,
    float* aux, float* aux2, int auxStride,
    int M, int N, int K, size_t sA, size_t sB, size_t sC)
{
    extern __shared__ char smem[];
    uint32_t sb;
    asm("{ .reg .u64 t; cvta.to.shared.u64 t, %1; cvt.u32.u64 %0, t; }" : "=r"(sb) : "l"(smem));
    const int b = blockIdx.z;
    hgemm_body<BIASM, EPI>(A + (size_t)b * sA, Bp + (size_t)b * sB, C + (size_t)b * sC,
                           bias, aux, aux2, auxStride,
                           M, N, K, blockIdx.y * 128, blockIdx.x * 128, b, sb);
}

// combined theta + phi + G projection launch (all K = CIN)
// per batch: 128 theta CTAs (32x4), 32 phi CTAs (8x4), 32 G CTAs (4x8)
__global__ void __launch_bounds__(128, 2) qkv_kernel(
    const float* __restrict__ theta_b, const float* __restrict__ phi_b,
    const float* __restrict__ g_b)
{
    extern __shared__ char smem[];
    uint32_t sb;
    asm("{ .reg .u64 t; cvta.to.shared.u64 t, %1; cvt.u32.u64 %0, t; }" : "=r"(sb) : "l"(smem));
    const int b = blockIdx.z;
    const int idx = blockIdx.x;
    if (idx < 128) {
        hgemm_body<0, 0>(d_xTh + (size_t)b * HW * CIN, d_w4h,
                         d_thetaTh + (size_t)b * HW * CI, theta_b,
                         nullptr, nullptr, 0,
                         HW, CI, CIN, (idx >> 2) * 128, (idx & 3) * 128, b, sb);
    } else if (idx < 160) {
        int j = idx - 128;
        hgemm_body<0, 0>(d_xpTh + (size_t)b * HWP * CIN, d_w4h + WSZ,
                         d_phiTh + (size_t)b * HWP * CI, phi_b,
                         nullptr, nullptr, 0,
                         HWP, CI, CIN, (j >> 2) * 128, (j & 3) * 128, b, sb);
    } else {
        int j = idx - 160;
        hgemm_body<1, 0>(d_w4h + 2 * WSZ, d_xpTh + (size_t)b * HWP * CIN,
                         d_Gh + (size_t)b * CI * HWP, g_b,
                         nullptr, nullptr, 0,
                         CI, HWP, CIN, (j >> 3) * 128, (j & 7) * 128, b, sb);
    }
}

// ---------------- final: out = x + gamma*(z-mean)*rstd + beta (BN inline) ----------------
__global__ void final_kernel(const float* __restrict__ x,
                             const float* __restrict__ gamma,
                             const float* __restrict__ beta,
                             float* __restrict__ out) {
    __shared__ float s[32][33];
    int b = blockIdx.z;
    int hw0 = blockIdx.x * 32, c0 = blockIdx.y * 32;
    int tx = threadIdx.x & 31, ty = threadIdx.x >> 5;
#pragma unroll
    for (int k = 0; k < 4; k++)
        s[ty + 8 * k][tx] =
            __half2float(d_zTh[((size_t)(b * HW) + hw0 + ty + 8 * k) * CIN + c0 + tx]);
    __syncthreads();
    const float inv_n = 1.0f / (float)(BATCH * HW);
#pragma unroll
    for (int k = 0; k < 4; k++) {
        int c = c0 + ty + 8 * k;
        float mean = d_bnsum[c] * inv_n;
        float var = d_bnsq[c] * inv_n - mean * mean;
        float rstd = rsqrtf(var + 1e-5f);
        size_t o = ((size_t)(b * CIN) + c) * HW + hw0 + tx;
        float sc = rstd * gamma[c];
        float off = beta[c] - mean * sc;
        out[o] = x[o] + s[tx][ty + 8 * k] * sc + off;
    }
}

extern "C" void kernel_launch(void* const* d_in, const int* in_sizes, int n_in,
                              void* d_out, int out_size) {
    const float* x       = (const float*)d_in[0];
    const float* theta_b = (const float*)d_in[2];
    const float* phi_b   = (const float*)d_in[4];
    const float* g_b     = (const float*)d_in[6];
    const float* wz_b    = (const float*)d_in[8];
    const float* gamma   = (const float*)d_in[9];
    const float* beta    = (const float*)d_in[10];
    float* out = (float*)d_out;

    __half *thetaTh, *phiTh, *Gh, *attnh, *yTh, *zTh, *w4h;
    float *rowsum, *bnsum, *bnsq;
    cudaGetSymbolAddress((void**)&thetaTh, d_thetaTh);
    cudaGetSymbolAddress((void**)&phiTh, d_phiTh);
    cudaGetSymbolAddress((void**)&Gh, d_Gh);
    cudaGetSymbolAddress((void**)&attnh, d_attnh);
    cudaGetSymbolAddress((void**)&yTh, d_yTh);
    cudaGetSymbolAddress((void**)&zTh, d_zTh);
    cudaGetSymbolAddress((void**)&w4h, d_w4h);
    cudaGetSymbolAddress((void**)&rowsum, d_rowsum);
    cudaGetSymbolAddress((void**)&bnsum, d_bnsum);
    cudaGetSymbolAddress((void**)&bnsq, d_bnsq);

    cudaFuncSetAttribute(qkv_kernel, cudaFuncAttributeMaxDynamicSharedMemorySize, HSM_TOTAL);
    cudaFuncSetAttribute(hgemm<0, 1>, cudaFuncAttributeMaxDynamicSharedMemorySize, HSM_TOTAL);
    cudaFuncSetAttribute(hgemm<0, 2>, cudaFuncAttributeMaxDynamicSharedMemorySize, HSM_TOTAL);
    cudaFuncSetAttribute(hgemm<0, 3>, cudaFuncAttributeMaxDynamicSharedMemorySize, HSM_TOTAL);

    // 0. prep: transpose+pool (z<8) and weight-round/zero (z==8)
    transpose_pool_kernel<<<dim3(32, CIN / 32, BATCH + 1), 256>>>(
        x, (const float*)d_in[1], (const float*)d_in[3], (const float*)d_in[5],
        (const float*)d_in[7]);

    // 1. combined theta/phi/G projections
    qkv_kernel<<<dim3(192, 1, BATCH), 128, HSM_TOTAL>>>(theta_b, phi_b, g_b);

    // 2. attnE[HW,HWP] = exp(thetaT . phiT^T / sqrt(CI)); rowsum accumulated
    hgemm<0, 1><<<dim3(HWP / 128, HW / 128, BATCH), 128, HSM_TOTAL>>>(
        thetaTh, phiTh, attnh, nullptr, rowsum, nullptr, HW,
        HW, HWP, CI, (size_t)HW * CI, (size_t)HWP * CI, (size_t)HW * HWP);

    // 3. yT[HW,CI] = (attnE . G^T) / rowsum[m]
    hgemm<0, 2><<<dim3(CI / 128, HW / 128, BATCH), 128, HSM_TOTAL>>>(
        attnh, Gh, yTh, nullptr, rowsum, nullptr, HW,
        HW, CI, HWP, (size_t)HW * HWP, (size_t)CI * HWP, (size_t)HW * CI);

    // 4. zTh[HW,CIN] = yT . wz_w^T + wz_b (per N); BN sums accumulated
    hgemm<0, 3><<<dim3(CIN / 128, HW / 128, BATCH), 128, HSM_TOTAL>>>(
        yTh, w4h + 3 * WSZ, zTh, wz_b, bnsum, bnsq, 0,
        HW, CIN, CI, (size_t)HW * CI, 0, (size_t)HW * CIN);

    // 5. out = x + gamma*(z-mean)*rstd + beta (BN finalize inline)
    final_kernel<<<dim3(HW / 32, CIN / 32, BATCH), 256>>>(x, gamma, beta, out);
}

// round 16
// speedup vs baseline: 1.6355x; 1.0026x over previous
#include <cuda_runtime.h>
#include <cuda_fp16.h>
#include <math.h>
#include <stdint.h>

#define BATCH 8
#define CIN 1024
#define CI 512
#define HW 4096     // 64*64
#define HWP 1024    // 32*32
#define WSZ 524288  // each weight matrix is 512*1024 elements

// ---- scratch (static device globals; no runtime allocation) ----
__device__ __half d_xTh[(size_t)BATCH * HW * CIN];
__device__ __half d_xpTh[(size_t)BATCH * HWP * CIN];
__device__ __half d_thetaTh[(size_t)BATCH * HW * CI];
__device__ __half d_phiTh[(size_t)BATCH * HWP * CI];
__device__ __half d_Gh[(size_t)BATCH * CI * HWP];      // [CI][HWP] per batch
__device__ __half d_attnh[(size_t)BATCH * HW * HWP];   // exp(scores), unnormalized
__device__ __half d_yTh[(size_t)BATCH * HW * CI];
__device__ __half d_zTh[(size_t)BATCH * HW * CIN];     // fp16 z
__device__ __half d_w4h[4 * WSZ];
__device__ float d_rowsum[(size_t)BATCH * HW];
__device__ float d_bnsum[CIN];
__device__ float d_bnsq[CIN];

__device__ __forceinline__ void cp16(uint32_t dst, const void* src) {
    asm volatile("cp.async.cg.shared.global [%0], [%1], 16;\n" :: "r"(dst), "l"(src));
}

// ---------------- fused prep: transpose+pool (z<8) / round weights + zero (z==8) ----------------
// Tile: 64 channels x 128 spatial (2 image rows). All fp16 writes are half2 (128B/warp).
__global__ void transpose_pool_kernel(const float* __restrict__ x,
                                      const float* __restrict__ w0, const float* __restrict__ w1,
                                      const float* __restrict__ w2, const float* __restrict__ w3) {
    int b = blockIdx.z;
    int tid = threadIdx.x;     // 256
    if (b == 8) {
        // weight rounding + accumulator zeroing slice (512 blocks x 1024 elems)
        int lin = blockIdx.y * 32 + blockIdx.x;   // 0..511
#pragma unroll
        for (int k = 0; k < 4; k++) {
            int i = lin * 1024 + tid + k * 256;
            d_w4h[0 * WSZ + i] = __float2half_rn(w0[i]);
            d_w4h[1 * WSZ + i] = __float2half_rn(w1[i]);
            d_w4h[2 * WSZ + i] = __float2half_rn(w2[i]);
            d_w4h[3 * WSZ + i] = __float2half_rn(w3[i]);
            if (i < BATCH * HW) d_rowsum[i] = 0.f;
            if (i < CIN) { d_bnsum[i] = 0.f; d_bnsq[i] = 0.f; }
        }
        return;
    }
    __shared__ float s[64][129];
    int pi = blockIdx.x;       // pooled row 0..31 (spatial rows 2*pi, 2*pi+1)
    int c0 = blockIdx.y * 64;
#pragma unroll
    for (int l = 0; l < 32; l++) {
        int idx = tid + l * 256;
        int c = idx >> 7, e = idx & 127;
        s[c][e] = x[((size_t)(b * CIN) + c0 + c) * HW + pi * 128 + e];
    }
    __syncthreads();
    // transposed fp16 write: hw = pi*128 + e, channels paired
#pragma unroll
    for (int l = 0; l < 16; l++) {
        int o = tid + l * 256;
        int e = o >> 5, cp = o & 31;
        __half2 h = __floats2half2_rn(s[2 * cp][e], s[2 * cp + 1][e]);
        *(__half2*)&d_xTh[((size_t)(b * HW) + pi * 128 + e) * CIN + c0 + 2 * cp] = h;
    }
    // pooled write: p = pi*32 + pj, channels paired
#pragma unroll
    for (int l = 0; l < 4; l++) {
        int o = tid + l * 256;
        int p = o >> 5, cp = o & 31;
        int c = 2 * cp;
        float v0 = fmaxf(fmaxf(s[c][2 * p], s[c][2 * p + 1]),
                         fmaxf(s[c][64 + 2 * p], s[c][64 + 2 * p + 1]));
        float v1 = fmaxf(fmaxf(s[c + 1][2 * p], s[c + 1][2 * p + 1]),
                         fmaxf(s[c + 1][64 + 2 * p], s[c + 1][64 + 2 * p + 1]));
        *(__half2*)&d_xpTh[((size_t)(b * HWP) + pi * 32 + p) * CIN + c0 + 2 * cp] =
            __floats2half2_rn(v0, v1);
    }
}

// ---------------- fp16 tensor-core GEMM body ----------------
// C[M,N] = alpha * A[M,K] . B[N,K]^T (+bias);  K contiguous, fp16 in/out.
// CTA tile 128x128, 4 warps (2x2), warp tile 64x64, BK=64 halves.
// 3-stage cp.async, 2 CTAs/SM.
// BIASM: bias indexed by M (else by N when bias != null).
// EPI: 0 plain; 1 exp + row-sum atomics; 2 row-divide; 3 BN sum/sumsq atomics.
#define NSTG 3
#define HSM_A_STAGE 16384
#define HSM_B_OFF   (NSTG * HSM_A_STAGE)
#define HSM_B_STAGE 16384
#define HSM_TOTAL   (NSTG * (HSM_A_STAGE + HSM_B_STAGE))   // 98304

template <int BIASM, int EPI>
__device__ __forceinline__ void hgemm_body(
    const __half* __restrict__ A, const __half* __restrict__ Bp,
    __half* __restrict__ C, const float* __restrict__ bias,
    float* aux, float* aux2, int auxStride,
    int M, int N, int K, int m0, int n0, int b, uint32_t sb)
{
    const int tid = threadIdx.x;
    const int wid = tid >> 5;
    const int lane = tid & 31;
    const int wm = wid & 1;
    const int wn = wid >> 1;

    const int g = lane >> 3;
    const int rr = lane & 7;
    const int row_off = ((g & 1) << 3) + rr;
    const int chunk_g = g >> 1;

    float acc[4][8][4];
#pragma unroll
    for (int mi = 0; mi < 4; mi++)
#pragma unroll
        for (int ni = 0; ni < 8; ni++)
#pragma unroll
            for (int v = 0; v < 4; v++) acc[mi][ni][v] = 0.f;

    const int NT = K / 64;

    auto prefetch = [&](int it, int buf) {
        const int k0 = it * 64;
        uint32_t sAb = sb + buf * HSM_A_STAGE;
        uint32_t sBb = sb + HSM_B_OFF + buf * HSM_B_STAGE;
#pragma unroll
        for (int i = 0; i < 8; i++) {
            int l = tid + i * 128;
            int r = l >> 3, c = l & 7;
            cp16(sAb + r * 128 + ((c ^ (r & 7)) << 4),
                 A + (size_t)(m0 + r) * K + k0 + c * 8);
        }
#pragma unroll
        for (int i = 0; i < 8; i++) {
            int l = tid + i * 128;
            int r = l >> 3, c = l & 7;
            cp16(sBb + r * 128 + ((c ^ (r & 7)) << 4),
                 Bp + (size_t)(n0 + r) * K + k0 + c * 8);
        }
    };

#pragma unroll
    for (int p = 0; p < NSTG - 1; p++) {
        if (p < NT) prefetch(p, p);
        asm volatile("cp.async.commit_group;\n" ::);
    }

    int buf = 0;
    for (int it = 0; it < NT; it++) {
        if (it + NSTG - 1 < NT) {
            int pb = it + NSTG - 1;
            prefetch(pb, pb % NSTG);
        }
        asm volatile("cp.async.commit_group;\n" ::);
        asm volatile("cp.async.wait_group %0;\n" :: "n"(NSTG - 1));
        __syncthreads();

        const uint32_t sA = sb + buf * HSM_A_STAGE;
        const uint32_t sB = sb + HSM_B_OFF + buf * HSM_B_STAGE;

#pragma unroll
        for (int kk = 0; kk < 4; kk++) {
            uint32_t af[4][4], bf[4][4];
#pragma unroll
            for (int mi = 0; mi < 4; mi++) {
                int m_loc = wm * 64 + mi * 16 + row_off;
                int chunk = kk * 2 + chunk_g;
                uint32_t addr = sA + m_loc * 128 + ((chunk ^ (m_loc & 7)) << 4);
                asm volatile("ldmatrix.sync.aligned.m8n8.x4.shared.b16 {%0,%1,%2,%3}, [%4];"
                             : "=r"(af[mi][0]), "=r"(af[mi][1]),
                               "=r"(af[mi][2]), "=r"(af[mi][3])
                             : "r"(addr));
            }
#pragma unroll
            for (int np = 0; np < 4; np++) {
                int n_loc = wn * 64 + np * 16 + row_off;
                int chunk = kk * 2 + chunk_g;
                uint32_t addr = sB + n_loc * 128 + ((chunk ^ (n_loc & 7)) << 4);
                asm volatile("ldmatrix.sync.aligned.m8n8.x4.shared.b16 {%0,%1,%2,%3}, [%4];"
                             : "=r"(bf[np][0]), "=r"(bf[np][1]),
                               "=r"(bf[np][2]), "=r"(bf[np][3])
                             : "r"(addr));
            }
#pragma unroll
            for (int mi = 0; mi < 4; mi++)
#pragma unroll
                for (int ni = 0; ni < 8; ni++) {
                    uint32_t b0 = bf[ni >> 1][(ni & 1)];
                    uint32_t b1 = bf[ni >> 1][2 + (ni & 1)];
                    asm volatile(
                        "mma.sync.aligned.m16n8k16.row.col.f32.f16.f16.f32 "
                        "{%0,%1,%2,%3}, {%4,%5,%6,%7}, {%8,%9}, {%0,%1,%2,%3};\n"
                        : "+f"(acc[mi][ni][0]), "+f"(acc[mi][ni][1]),
                          "+f"(acc[mi][ni][2]), "+f"(acc[mi][ni][3])
                        : "r"(af[mi][0]), "r"(af[mi][1]), "r"(af[mi][2]), "r"(af[mi][3]),
                          "r"(b0), "r"(b1));
                }
        }
        __syncthreads();
        if (++buf == NSTG) buf = 0;
    }

    // ---- epilogue ----
    float csum[8][2], csq[8][2];
    if (EPI == 3) {
#pragma unroll
        for (int ni = 0; ni < 8; ni++) {
            csum[ni][0] = csum[ni][1] = 0.f;
            csq[ni][0] = csq[ni][1] = 0.f;
        }
    }
    const float alpha = (EPI == 1) ? 0.044194173824159216f /* 1/sqrt(512) */ : 1.0f;
#pragma unroll
    for (int mi = 0; mi < 4; mi++) {
        int m = m0 + wm * 64 + mi * 16 + (lane >> 2);
        float bm0 = 0.f, bm1 = 0.f;
        if (BIASM && bias) { bm0 = bias[m]; bm1 = bias[m + 8]; }
        float inv0 = 1.f, inv1 = 1.f;
        if (EPI == 2) {
            inv0 = 1.f / aux[(size_t)b * auxStride + m];
            inv1 = 1.f / aux[(size_t)b * auxStride + m + 8];
        }
        float rs0 = 0.f, rs1 = 0.f;
#pragma unroll
        for (int ni = 0; ni < 8; ni++) {
            int n = n0 + wn * 64 + ni * 8 + (lane & 3) * 2;
            float v0 = acc[mi][ni][0] * alpha;
            float v1 = acc[mi][ni][1] * alpha;
            float v2 = acc[mi][ni][2] * alpha;
            float v3 = acc[mi][ni][3] * alpha;
            if (BIASM) {
                v0 += bm0; v1 += bm0; v2 += bm1; v3 += bm1;
            } else if (bias) {
                float bn0 = bias[n], bn1 = bias[n + 1];
                v0 += bn0; v1 += bn1; v2 += bn0; v3 += bn1;
            }
            if (EPI == 1) {
                v0 = __expf(v0); v1 = __expf(v1);
                v2 = __expf(v2); v3 = __expf(v3);
                rs0 += v0 + v1;
                rs1 += v2 + v3;
            }
            if (EPI == 2) {
                v0 *= inv0; v1 *= inv0; v2 *= inv1; v3 *= inv1;
            }
            if (EPI == 3) {
                csum[ni][0] += v0 + v2;  csum[ni][1] += v1 + v3;
                csq[ni][0] += v0 * v0 + v2 * v2;
                csq[ni][1] += v1 * v1 + v3 * v3;
            }
            *(__half2*)&C[(size_t)m * N + n] = __floats2half2_rn(v0, v1);
            *(__half2*)&C[(size_t)(m + 8) * N + n] = __floats2half2_rn(v2, v3);
        }
        if (EPI == 1) {
            rs0 += __shfl_xor_sync(0xffffffffu, rs0, 1);
            rs0 += __shfl_xor_sync(0xffffffffu, rs0, 2);
            rs1 += __shfl_xor_sync(0xffffffffu, rs1, 1);
            rs1 += __shfl_xor_sync(0xffffffffu, rs1, 2);
            if ((lane & 3) == 0) {
                atomicAdd(&aux[(size_t)b * auxStride + m], rs0);
                atomicAdd(&aux[(size_t)b * auxStride + m + 8], rs1);
            }
        }
    }
    if (EPI == 3) {
#pragma unroll
        for (int ni = 0; ni < 8; ni++) {
#pragma unroll
            for (int h = 0; h < 2; h++) {
                float s = csum[ni][h], q = csq[ni][h];
                s += __shfl_xor_sync(0xffffffffu, s, 4);
                s += __shfl_xor_sync(0xffffffffu, s, 8);
                s += __shfl_xor_sync(0xffffffffu, s, 16);
                q += __shfl_xor_sync(0xffffffffu, q, 4);
                q += __shfl_xor_sync(0xffffffffu, q, 8);
                q += __shfl_xor_sync(0xffffffffu, q, 16);
                if ((lane >> 2) == 0) {
                    int n = n0 + wn * 64 + ni * 8 + (lane & 3) * 2 + h;
                    atomicAdd(&aux[n], s);
                    atomicAdd(&aux2[n], q);
                }
            }
        }
    }
}

// generic single-problem wrapper
template <int BIASM, int EPI>
__global__ void __launch_bounds__(128, 2) hgemm(
    const __half* __restrict__ A, const __half* __restrict__ Bp,
    __half* __restrict__ C, const float* __restrict__ bias,
    float* aux, float* aux2, int auxStride,
    int M, int N, int K, size_t sA, size_t sB, size_t sC)
{
    extern __shared__ char smem[];
    uint32_t sb;
    asm("{ .reg .u64 t; cvta.to.shared.u64 t, %1; cvt.u32.u64 %0, t; }" : "=r"(sb) : "l"(smem));
    const int b = blockIdx.z;
    hgemm_body<BIASM, EPI>(A + (size_t)b * sA, Bp + (size_t)b * sB, C + (size_t)b * sC,
                           bias, aux, aux2, auxStride,
                           M, N, K, blockIdx.y * 128, blockIdx.x * 128, b, sb);
}

// combined theta + phi + G projection launch (all K = CIN)
// per batch: 128 theta CTAs (32x4), 32 phi CTAs (8x4), 32 G CTAs (4x8)
__global__ void __launch_bounds__(128, 2) qkv_kernel(
    const float* __restrict__ theta_b, const float* __restrict__ phi_b,
    const float* __restrict__ g_b)
{
    extern __shared__ char smem[];
    uint32_t sb;
    asm("{ .reg .u64 t; cvta.to.shared.u64 t, %1; cvt.u32.u64 %0, t; }" : "=r"(sb) : "l"(smem));
    const int b = blockIdx.z;
    const int idx = blockIdx.x;
    if (idx < 128) {
        hgemm_body<0, 0>(d_xTh + (size_t)b * HW * CIN, d_w4h,
                         d_thetaTh + (size_t)b * HW * CI, theta_b,
                         nullptr, nullptr, 0,
                         HW, CI, CIN, (idx >> 2) * 128, (idx & 3) * 128, b, sb);
    } else if (idx < 160) {
        int j = idx - 128;
        hgemm_body<0, 0>(d_xpTh + (size_t)b * HWP * CIN, d_w4h + WSZ,
                         d_phiTh + (size_t)b * HWP * CI, phi_b,
                         nullptr, nullptr, 0,
                         HWP, CI, CIN, (j >> 2) * 128, (j & 3) * 128, b, sb);
    } else {
        int j = idx - 160;
        hgemm_body<1, 0>(d_w4h + 2 * WSZ, d_xpTh + (size_t)b * HWP * CIN,
                         d_Gh + (size_t)b * CI * HWP, g_b,
                         nullptr, nullptr, 0,
                         CI, HWP, CIN, (j >> 3) * 128, (j & 7) * 128, b, sb);
    }
}

// ---------------- final: out = x + gamma*(z-mean)*rstd + beta (BN inline) ----------------
// Tile: 32 hw x 64 channels; zTh read as half2 (128B/warp).
__global__ void final_kernel(const float* __restrict__ x,
                             const float* __restrict__ gamma,
                             const float* __restrict__ beta,
                             float* __restrict__ out) {
    __shared__ float s[32][66];
    int b = blockIdx.z;
    int hw0 = blockIdx.x * 32, c0 = blockIdx.y * 64;
    int tid = threadIdx.x;  // 256
#pragma unroll
    for (int l = 0; l < 4; l++) {
        int o = tid + l * 256;
        int hw = o >> 5, cp = o & 31;
        __half2 h = *(const __half2*)&d_zTh[((size_t)(b * HW) + hw0 + hw) * CIN + c0 + 2 * cp];
        float2 f = __half22float2(h);
        s[hw][2 * cp] = f.x;
        s[hw][2 * cp + 1] = f.y;
    }
    __syncthreads();
    const float inv_n = 1.0f / (float)(BATCH * HW);
#pragma unroll
    for (int l = 0; l < 8; l++) {
        int o = tid + l * 256;
        int cl = o >> 5, tx = o & 31;
        int c = c0 + cl;
        float mean = d_bnsum[c] * inv_n;
        float var = d_bnsq[c] * inv_n - mean * mean;
        float rstd = rsqrtf(var + 1e-5f);
        float sc = rstd * gamma[c];
        float off = beta[c] - mean * sc;
        size_t oidx = ((size_t)(b * CIN) + c) * HW + hw0 + tx;
        out[oidx] = x[oidx] + s[tx][cl] * sc + off;
    }
}

extern "C" void kernel_launch(void* const* d_in, const int* in_sizes, int n_in,
                              void* d_out, int out_size) {
    const float* x       = (const float*)d_in[0];
    const float* theta_b = (const float*)d_in[2];
    const float* phi_b   = (const float*)d_in[4];
    const float* g_b     = (const float*)d_in[6];
    const float* wz_b    = (const float*)d_in[8];
    const float* gamma   = (const float*)d_in[9];
    const float* beta    = (const float*)d_in[10];
    float* out = (float*)d_out;

    __half *thetaTh, *phiTh, *Gh, *attnh, *yTh, *zTh, *w4h;
    float *rowsum, *bnsum, *bnsq;
    cudaGetSymbolAddress((void**)&thetaTh, d_thetaTh);
    cudaGetSymbolAddress((void**)&phiTh, d_phiTh);
    cudaGetSymbolAddress((void**)&Gh, d_Gh);
    cudaGetSymbolAddress((void**)&attnh, d_attnh);
    cudaGetSymbolAddress((void**)&yTh, d_yTh);
    cudaGetSymbolAddress((void**)&zTh, d_zTh);
    cudaGetSymbolAddress((void**)&w4h, d_w4h);
    cudaGetSymbolAddress((void**)&rowsum, d_rowsum);
    cudaGetSymbolAddress((void**)&bnsum, d_bnsum);
    cudaGetSymbolAddress((void**)&bnsq, d_bnsq);

    cudaFuncSetAttribute(qkv_kernel, cudaFuncAttributeMaxDynamicSharedMemorySize, HSM_TOTAL);
    cudaFuncSetAttribute(hgemm<0, 1>, cudaFuncAttributeMaxDynamicSharedMemorySize, HSM_TOTAL);
    cudaFuncSetAttribute(hgemm<0, 2>, cudaFuncAttributeMaxDynamicSharedMemorySize, HSM_TOTAL);
    cudaFuncSetAttribute(hgemm<0, 3>, cudaFuncAttributeMaxDynamicSharedMemorySize, HSM_TOTAL);

    // 0. prep: transpose+pool (z<8) and weight-round/zero (z==8)
    transpose_pool_kernel<<<dim3(32, CIN / 64, BATCH + 1), 256>>>(
        x, (const float*)d_in[1], (const float*)d_in[3], (const float*)d_in[5],
        (const float*)d_in[7]);

    // 1. combined theta/phi/G projections
    qkv_kernel<<<dim3(192, 1, BATCH), 128, HSM_TOTAL>>>(theta_b, phi_b, g_b);

    // 2. attnE[HW,HWP] = exp(thetaT . phiT^T / sqrt(CI)); rowsum accumulated
    hgemm<0, 1><<<dim3(HWP / 128, HW / 128, BATCH), 128, HSM_TOTAL>>>(
        thetaTh, phiTh, attnh, nullptr, rowsum, nullptr, HW,
        HW, HWP, CI, (size_t)HW * CI, (size_t)HWP * CI, (size_t)HW * HWP);

    // 3. yT[HW,CI] = (attnE . G^T) / rowsum[m]
    hgemm<0, 2><<<dim3(CI / 128, HW / 128, BATCH), 128, HSM_TOTAL>>>(
        attnh, Gh, yTh, nullptr, rowsum, nullptr, HW,
        HW, CI, HWP, (size_t)HW * HWP, (size_t)CI * HWP, (size_t)HW * CI);

    // 4. zTh[HW,CIN] = yT . wz_w^T + wz_b (per N); BN sums accumulated
    hgemm<0, 3><<<dim3(CIN / 128, HW / 128, BATCH), 128, HSM_TOTAL>>>(
        yTh, w4h + 3 * WSZ, zTh, wz_b, bnsum, bnsq, 0,
        HW, CIN, CI, (size_t)HW * CI, 0, (size_t)HW * CIN);

    // 5. out = x + gamma*(z-mean)*rstd + beta (BN finalize inline)
    final_kernel<<<dim3(HW / 32, CIN / 64, BATCH), 256>>>(x, gamma, beta, out);
}

// round 17
// speedup vs baseline: 1.7259x; 1.0552x over previous
#include <cuda_runtime.h>
#include <cuda_fp16.h>
#include <math.h>
#include <stdint.h>

#define BATCH 8
#define CIN 1024
#define CI 512
#define HW 4096     // 64*64
#define HWP 1024    // 32*32
#define WSZ 524288  // each weight matrix is 512*1024 elements

// ---- scratch (static device globals; no runtime allocation) ----
__device__ __half d_xTh[(size_t)BATCH * HW * CIN];
__device__ __half d_xpTh[(size_t)BATCH * HWP * CIN];
__device__ __half d_thetaTh[(size_t)BATCH * HW * CI];
__device__ __half d_phiTh[(size_t)BATCH * HWP * CI];
__device__ __half d_Gh[(size_t)BATCH * CI * HWP];      // [CI][HWP] per batch
__device__ __half d_attnh[(size_t)BATCH * HW * HWP];   // exp(scores), unnormalized
__device__ __half d_yTh[(size_t)BATCH * HW * CI];
__device__ __half d_zTh[(size_t)BATCH * HW * CIN];     // fp16 z
__device__ __half d_w4h[4 * WSZ];
__device__ float d_rowsum[(size_t)BATCH * HW];
__device__ float d_bnsum[CIN];
__device__ float d_bnsq[CIN];

// ---- second stream + fork/join events, created before main (no mem-checkpoint window) ----
static cudaStream_t g_s1 = nullptr;
static cudaEvent_t g_eF = nullptr, g_eZ0 = nullptr, g_eZ1 = nullptr, g_eJ = nullptr;
namespace {
struct StreamInit {
    StreamInit() {
        if (cudaStreamCreateWithFlags(&g_s1, cudaStreamNonBlocking) != cudaSuccess) {
            g_s1 = nullptr;
            return;
        }
        cudaEventCreateWithFlags(&g_eF, cudaEventDisableTiming);
        cudaEventCreateWithFlags(&g_eZ0, cudaEventDisableTiming);
        cudaEventCreateWithFlags(&g_eZ1, cudaEventDisableTiming);
        cudaEventCreateWithFlags(&g_eJ, cudaEventDisableTiming);
    }
};
StreamInit g_stream_init;
}

__device__ __forceinline__ void cp16(uint32_t dst, const void* src) {
    asm volatile("cp.async.cg.shared.global [%0], [%1], 16;\n" :: "r"(dst), "l"(src));
}

// ---------------- fused prep: transpose+pool (z<8) / round weights + zero (z==8) ----------------
__global__ void transpose_pool_kernel(const float* __restrict__ x,
                                      const float* __restrict__ w0, const float* __restrict__ w1,
                                      const float* __restrict__ w2, const float* __restrict__ w3) {
    int b = blockIdx.z;
    int tid = threadIdx.x;     // 256
    if (b == 8) {
        int lin = blockIdx.y * 32 + blockIdx.x;   // 0..511
#pragma unroll
        for (int k = 0; k < 4; k++) {
            int i = lin * 1024 + tid + k * 256;
            d_w4h[0 * WSZ + i] = __float2half_rn(w0[i]);
            d_w4h[1 * WSZ + i] = __float2half_rn(w1[i]);
            d_w4h[2 * WSZ + i] = __float2half_rn(w2[i]);
            d_w4h[3 * WSZ + i] = __float2half_rn(w3[i]);
            if (i < BATCH * HW) d_rowsum[i] = 0.f;
            if (i < CIN) { d_bnsum[i] = 0.f; d_bnsq[i] = 0.f; }
        }
        return;
    }
    __shared__ float s[64][129];
    int pi = blockIdx.x;       // pooled row 0..31
    int c0 = blockIdx.y * 64;
#pragma unroll
    for (int l = 0; l < 32; l++) {
        int idx = tid + l * 256;
        int c = idx >> 7, e = idx & 127;
        s[c][e] = x[((size_t)(b * CIN) + c0 + c) * HW + pi * 128 + e];
    }
    __syncthreads();
#pragma unroll
    for (int l = 0; l < 16; l++) {
        int o = tid + l * 256;
        int e = o >> 5, cp = o & 31;
        __half2 h = __floats2half2_rn(s[2 * cp][e], s[2 * cp + 1][e]);
        *(__half2*)&d_xTh[((size_t)(b * HW) + pi * 128 + e) * CIN + c0 + 2 * cp] = h;
    }
#pragma unroll
    for (int l = 0; l < 4; l++) {
        int o = tid + l * 256;
        int p = o >> 5, cp = o & 31;
        int c = 2 * cp;
        float v0 = fmaxf(fmaxf(s[c][2 * p], s[c][2 * p + 1]),
                         fmaxf(s[c][64 + 2 * p], s[c][64 + 2 * p + 1]));
        float v1 = fmaxf(fmaxf(s[c + 1][2 * p], s[c + 1][2 * p + 1]),
                         fmaxf(s[c + 1][64 + 2 * p], s[c + 1][64 + 2 * p + 1]));
        *(__half2*)&d_xpTh[((size_t)(b * HWP) + pi * 32 + p) * CIN + c0 + 2 * cp] =
            __floats2half2_rn(v0, v1);
    }
}

// ---------------- fp16 tensor-core GEMM body ----------------
#define NSTG 3
#define HSM_A_STAGE 16384
#define HSM_B_OFF   (NSTG * HSM_A_STAGE)
#define HSM_B_STAGE 16384
#define HSM_TOTAL   (NSTG * (HSM_A_STAGE + HSM_B_STAGE))   // 98304

template <int BIASM, int EPI>
__device__ __forceinline__ void hgemm_body(
    const __half* __restrict__ A, const __half* __restrict__ Bp,
    __half* __restrict__ C, const float* __restrict__ bias,
    float* aux, float* aux2, int auxStride,
    int M, int N, int K, int m0, int n0, int b, uint32_t sb)
{
    const int tid = threadIdx.x;
    const int wid = tid >> 5;
    const int lane = tid & 31;
    const int wm = wid & 1;
    const int wn = wid >> 1;

    const int g = lane >> 3;
    const int rr = lane & 7;
    const int row_off = ((g & 1) << 3) + rr;
    const int chunk_g = g >> 1;

    float acc[4][8][4];
#pragma unroll
    for (int mi = 0; mi < 4; mi++)
#pragma unroll
        for (int ni = 0; ni < 8; ni++)
#pragma unroll
            for (int v = 0; v < 4; v++) acc[mi][ni][v] = 0.f;

    const int NT = K / 64;

    auto prefetch = [&](int it, int buf) {
        const int k0 = it * 64;
        uint32_t sAb = sb + buf * HSM_A_STAGE;
        uint32_t sBb = sb + HSM_B_OFF + buf * HSM_B_STAGE;
#pragma unroll
        for (int i = 0; i < 8; i++) {
            int l = tid + i * 128;
            int r = l >> 3, c = l & 7;
            cp16(sAb + r * 128 + ((c ^ (r & 7)) << 4),
                 A + (size_t)(m0 + r) * K + k0 + c * 8);
        }
#pragma unroll
        for (int i = 0; i < 8; i++) {
            int l = tid + i * 128;
            int r = l >> 3, c = l & 7;
            cp16(sBb + r * 128 + ((c ^ (r & 7)) << 4),
                 Bp + (size_t)(n0 + r) * K + k0 + c * 8);
        }
    };

#pragma unroll
    for (int p = 0; p < NSTG - 1; p++) {
        if (p < NT) prefetch(p, p);
        asm volatile("cp.async.commit_group;\n" ::);
    }

    int buf = 0;
    for (int it = 0; it < NT; it++) {
        if (it + NSTG - 1 < NT) {
            int pb = it + NSTG - 1;
            prefetch(pb, pb % NSTG);
        }
        asm volatile("cp.async.commit_group;\n" ::);
        asm volatile("cp.async.wait_group %0;\n" :: "n"(NSTG - 1));
        __syncthreads();

        const uint32_t sA = sb + buf * HSM_A_STAGE;
        const uint32_t sB = sb + HSM_B_OFF + buf * HSM_B_STAGE;

#pragma unroll
        for (int kk = 0; kk < 4; kk++) {
            uint32_t af[4][4], bf[4][4];
#pragma unroll
            for (int mi = 0; mi < 4; mi++) {
                int m_loc = wm * 64 + mi * 16 + row_off;
                int chunk = kk * 2 + chunk_g;
                uint32_t addr = sA + m_loc * 128 + ((chunk ^ (m_loc & 7)) << 4);
                asm volatile("ldmatrix.sync.aligned.m8n8.x4.shared.b16 {%0,%1,%2,%3}, [%4];"
                             : "=r"(af[mi][0]), "=r"(af[mi][1]),
                               "=r"(af[mi][2]), "=r"(af[mi][3])
                             : "r"(addr));
            }
#pragma unroll
            for (int np = 0; np < 4; np++) {
                int n_loc = wn * 64 + np * 16 + row_off;
                int chunk = kk * 2 + chunk_g;
                uint32_t addr = sB + n_loc * 128 + ((chunk ^ (n_loc & 7)) << 4);
                asm volatile("ldmatrix.sync.aligned.m8n8.x4.shared.b16 {%0,%1,%2,%3}, [%4];"
                             : "=r"(bf[np][0]), "=r"(bf[np][1]),
                               "=r"(bf[np][2]), "=r"(bf[np][3])
                             : "r"(addr));
            }
#pragma unroll
            for (int mi = 0; mi < 4; mi++)
#pragma unroll
                for (int ni = 0; ni < 8; ni++) {
                    uint32_t b0 = bf[ni >> 1][(ni & 1)];
                    uint32_t b1 = bf[ni >> 1][2 + (ni & 1)];
                    asm volatile(
                        "mma.sync.aligned.m16n8k16.row.col.f32.f16.f16.f32 "
                        "{%0,%1,%2,%3}, {%4,%5,%6,%7}, {%8,%9}, {%0,%1,%2,%3};\n"
                        : "+f"(acc[mi][ni][0]), "+f"(acc[mi][ni][1]),
                          "+f"(acc[mi][ni][2]), "+f"(acc[mi][ni][3])
                        : "r"(af[mi][0]), "r"(af[mi][1]), "r"(af[mi][2]), "r"(af[mi][3]),
                          "r"(b0), "r"(b1));
                }
        }
        __syncthreads();
        if (++buf == NSTG) buf = 0;
    }

    // ---- epilogue ----
    float csum[8][2], csq[8][2];
    if (EPI == 3) {
#pragma unroll
        for (int ni = 0; ni < 8; ni++) {
            csum[ni][0] = csum[ni][1] = 0.f;
            csq[ni][0] = csq[ni][1] = 0.f;
        }
    }
    const float alpha = (EPI == 1) ? 0.044194173824159216f /* 1/sqrt(512) */ : 1.0f;
#pragma unroll
    for (int mi = 0; mi < 4; mi++) {
        int m = m0 + wm * 64 + mi * 16 + (lane >> 2);
        float bm0 = 0.f, bm1 = 0.f;
        if (BIASM && bias) { bm0 = bias[m]; bm1 = bias[m + 8]; }
        float inv0 = 1.f, inv1 = 1.f;
        if (EPI == 2) {
            inv0 = 1.f / aux[(size_t)b * auxStride + m];
            inv1 = 1.f / aux[(size_t)b * auxStride + m + 8];
        }
        float rs0 = 0.f, rs1 = 0.f;
#pragma unroll
        for (int ni = 0; ni < 8; ni++) {
            int n = n0 + wn * 64 + ni * 8 + (lane & 3) * 2;
            float v0 = acc[mi][ni][0] * alpha;
            float v1 = acc[mi][ni][1] * alpha;
            float v2 = acc[mi][ni][2] * alpha;
            float v3 = acc[mi][ni][3] * alpha;
            if (BIASM) {
                v0 += bm0; v1 += bm0; v2 += bm1; v3 += bm1;
            } else if (bias) {
                float bn0 = bias[n], bn1 = bias[n + 1];
                v0 += bn0; v1 += bn1; v2 += bn0; v3 += bn1;
            }
            if (EPI == 1) {
                v0 = __expf(v0); v1 = __expf(v1);
                v2 = __expf(v2); v3 = __expf(v3);
                rs0 += v0 + v1;
                rs1 += v2 + v3;
            }
            if (EPI == 2) {
                v0 *= inv0; v1 *= inv0; v2 *= inv1; v3 *= inv1;
            }
            if (EPI == 3) {
                csum[ni][0] += v0 + v2;  csum[ni][1] += v1 + v3;
                csq[ni][0] += v0 * v0 + v2 * v2;
                csq[ni][1] += v1 * v1 + v3 * v3;
            }
            *(__half2*)&C[(size_t)m * N + n] = __floats2half2_rn(v0, v1);
            *(__half2*)&C[(size_t)(m + 8) * N + n] = __floats2half2_rn(v2, v3);
        }
        if (EPI == 1) {
            rs0 += __shfl_xor_sync(0xffffffffu, rs0, 1);
            rs0 += __shfl_xor_sync(0xffffffffu, rs0, 2);
            rs1 += __shfl_xor_sync(0xffffffffu, rs1, 1);
            rs1 += __shfl_xor_sync(0xffffffffu, rs1, 2);
            if ((lane & 3) == 0) {
                atomicAdd(&aux[(size_t)b * auxStride + m], rs0);
                atomicAdd(&aux[(size_t)b * auxStride + m + 8], rs1);
            }
        }
    }
    if (EPI == 3) {
#pragma unroll
        for (int ni = 0; ni < 8; ni++) {
#pragma unroll
            for (int h = 0; h < 2; h++) {
                float s = csum[ni][h], q = csq[ni][h];
                s += __shfl_xor_sync(0xffffffffu, s, 4);
                s += __shfl_xor_sync(0xffffffffu, s, 8);
                s += __shfl_xor_sync(0xffffffffu, s, 16);
                q += __shfl_xor_sync(0xffffffffu, q, 4);
                q += __shfl_xor_sync(0xffffffffu, q, 8);
                q += __shfl_xor_sync(0xffffffffu, q, 16);
                if ((lane >> 2) == 0) {
                    int n = n0 + wn * 64 + ni * 8 + (lane & 3) * 2 + h;
                    atomicAdd(&aux[n], s);
                    atomicAdd(&aux2[n], q);
                }
            }
        }
    }
}

// generic single-problem wrapper
template <int BIASM, int EPI>
__global__ void __launch_bounds__(128, 2) hgemm(
    const __half* __restrict__ A, const __half* __restrict__ Bp,
    __half* __restrict__ C, const float* __restrict__ bias,
    float* aux, float* aux2, int auxStride,
    int M, int N, int K, size_t sA, size_t sB, size_t sC)
{
    extern __shared__ char smem[];
    uint32_t sb;
    asm("{ .reg .u64 t; cvta.to.shared.u64 t, %1; cvt.u32.u64 %0, t; }" : "=r"(sb) : "l"(smem));
    const int b = blockIdx.z;
    hgemm_body<BIASM, EPI>(A + (size_t)b * sA, Bp + (size_t)b * sB, C + (size_t)b * sC,
                           bias, aux, aux2, auxStride,
                           M, N, K, blockIdx.y * 128, blockIdx.x * 128, b, sb);
}

// combined theta + phi + G projection launch (all K = CIN), batches [b0, b0+gridDim.z)
__global__ void __launch_bounds__(128, 2) qkv_kernel(
    const float* __restrict__ theta_b, const float* __restrict__ phi_b,
    const float* __restrict__ g_b, int b0)
{
    extern __shared__ char smem[];
    uint32_t sb;
    asm("{ .reg .u64 t; cvta.to.shared.u64 t, %1; cvt.u32.u64 %0, t; }" : "=r"(sb) : "l"(smem));
    const int b = blockIdx.z + b0;
    const int idx = blockIdx.x;
    if (idx < 128) {
        hgemm_body<0, 0>(d_xTh + (size_t)b * HW * CIN, d_w4h,
                         d_thetaTh + (size_t)b * HW * CI, theta_b,
                         nullptr, nullptr, 0,
                         HW, CI, CIN, (idx >> 2) * 128, (idx & 3) * 128, b, sb);
    } else if (idx < 160) {
        int j = idx - 128;
        hgemm_body<0, 0>(d_xpTh + (size_t)b * HWP * CIN, d_w4h + WSZ,
                         d_phiTh + (size_t)b * HWP * CI, phi_b,
                         nullptr, nullptr, 0,
                         HWP, CI, CIN, (j >> 2) * 128, (j & 3) * 128, b, sb);
    } else {
        int j = idx - 160;
        hgemm_body<1, 0>(d_w4h + 2 * WSZ, d_xpTh + (size_t)b * HWP * CIN,
                         d_Gh + (size_t)b * CI * HWP, g_b,
                         nullptr, nullptr, 0,
                         CI, HWP, CIN, (j >> 3) * 128, (j & 7) * 128, b, sb);
    }
}

// ---------------- final: out = x + gamma*(z-mean)*rstd + beta (BN inline) ----------------
__global__ void final_kernel(const float* __restrict__ x,
                             const float* __restrict__ gamma,
                             const float* __restrict__ beta,
                             float* __restrict__ out, int b0) {
    __shared__ float s[32][66];
    int b = blockIdx.z + b0;
    int hw0 = blockIdx.x * 32, c0 = blockIdx.y * 64;
    int tid = threadIdx.x;  // 256
#pragma unroll
    for (int l = 0; l < 4; l++) {
        int o = tid + l * 256;
        int hw = o >> 5, cp = o & 31;
        __half2 h = *(const __half2*)&d_zTh[((size_t)(b * HW) + hw0 + hw) * CIN + c0 + 2 * cp];
        float2 f = __half22float2(h);
        s[hw][2 * cp] = f.x;
        s[hw][2 * cp + 1] = f.y;
    }
    __syncthreads();
    const float inv_n = 1.0f / (float)(BATCH * HW);
#pragma unroll
    for (int l = 0; l < 8; l++) {
        int o = tid + l * 256;
        int cl = o >> 5, tx = o & 31;
        int c = c0 + cl;
        float mean = d_bnsum[c] * inv_n;
        float var = d_bnsq[c] * inv_n - mean * mean;
        float rstd = rsqrtf(var + 1e-5f);
        float sc = rstd * gamma[c];
        float off = beta[c] - mean * sc;
        size_t oidx = ((size_t)(b * CIN) + c) * HW + hw0 + tx;
        out[oidx] = x[oidx] + s[tx][cl] * sc + off;
    }
}

extern "C" void kernel_launch(void* const* d_in, const int* in_sizes, int n_in,
                              void* d_out, int out_size) {
    const float* x       = (const float*)d_in[0];
    const float* theta_b = (const float*)d_in[2];
    const float* phi_b   = (const float*)d_in[4];
    const float* g_b     = (const float*)d_in[6];
    const float* wz_b    = (const float*)d_in[8];
    const float* gamma   = (const float*)d_in[9];
    const float* beta    = (const float*)d_in[10];
    float* out = (float*)d_out;

    __half *thetaTh, *phiTh, *Gh, *attnh, *yTh, *zTh, *w4h;
    float *rowsum, *bnsum, *bnsq;
    cudaGetSymbolAddress((void**)&thetaTh, d_thetaTh);
    cudaGetSymbolAddress((void**)&phiTh, d_phiTh);
    cudaGetSymbolAddress((void**)&Gh, d_Gh);
    cudaGetSymbolAddress((void**)&attnh, d_attnh);
    cudaGetSymbolAddress((void**)&yTh, d_yTh);
    cudaGetSymbolAddress((void**)&zTh, d_zTh);
    cudaGetSymbolAddress((void**)&w4h, d_w4h);
    cudaGetSymbolAddress((void**)&rowsum, d_rowsum);
    cudaGetSymbolAddress((void**)&bnsum, d_bnsum);
    cudaGetSymbolAddress((void**)&bnsq, d_bnsq);

    cudaFuncSetAttribute(qkv_kernel, cudaFuncAttributeMaxDynamicSharedMemorySize, HSM_TOTAL);
    cudaFuncSetAttribute(hgemm<0, 1>, cudaFuncAttributeMaxDynamicSharedMemorySize, HSM_TOTAL);
    cudaFuncSetAttribute(hgemm<0, 2>, cudaFuncAttributeMaxDynamicSharedMemorySize, HSM_TOTAL);
    cudaFuncSetAttribute(hgemm<0, 3>, cudaFuncAttributeMaxDynamicSharedMemorySize, HSM_TOTAL);

    const bool dual = (g_s1 != nullptr && g_eF && g_eZ0 && g_eZ1 && g_eJ);
    cudaStream_t s0 = 0;
    cudaStream_t s1 = dual ? g_s1 : (cudaStream_t)0;
    const int HB = dual ? 4 : BATCH;     // batches per chain
    const int NH = dual ? 2 : 1;         // number of chains

    // 0. prep on the origin stream
    transpose_pool_kernel<<<dim3(32, CIN / 64, BATCH + 1), 256, 0, s0>>>(
        x, (const float*)d_in[1], (const float*)d_in[3], (const float*)d_in[5],
        (const float*)d_in[7]);

    if (dual) {
        cudaEventRecord(g_eF, s0);
        cudaStreamWaitEvent(s1, g_eF, 0);
    }

    for (int h = 0; h < NH; h++) {
        cudaStream_t s = (h == 0) ? s0 : s1;
        const int bo = h * HB;
        const size_t oT = (size_t)bo * HW * CI;
        const size_t oA = (size_t)bo * HW * HWP;

        // 1. projections
        qkv_kernel<<<dim3(192, 1, HB), 128, HSM_TOTAL, s>>>(theta_b, phi_b, g_b, bo);

        // 2. attnE = exp(theta . phi^T / sqrt(CI)); rowsum accumulated
        hgemm<0, 1><<<dim3(HWP / 128, HW / 128, HB), 128, HSM_TOTAL, s>>>(
            thetaTh + oT, phiTh + (size_t)bo * HWP * CI, attnh + oA, nullptr,
            rowsum + (size_t)bo * HW, nullptr, HW,
            HW, HWP, CI, (size_t)HW * CI, (size_t)HWP * CI, (size_t)HW * HWP);

        // 3. yT = (attnE . G^T) / rowsum[m]
        hgemm<0, 2><<<dim3(CI / 128, HW / 128, HB), 128, HSM_TOTAL, s>>>(
            attnh + oA, Gh + (size_t)bo * CI * HWP, yTh + oT, nullptr,
            rowsum + (size_t)bo * HW, nullptr, HW,
            HW, CI, HWP, (size_t)HW * HWP, (size_t)CI * HWP, (size_t)HW * CI);

        // 4. zTh = yT . wz_w^T + wz_b; BN sums accumulated (shared atomics)
        hgemm<0, 3><<<dim3(CIN / 128, HW / 128, HB), 128, HSM_TOTAL, s>>>(
            yTh + oT, w4h + 3 * WSZ, zTh + (size_t)bo * HW * CIN, wz_b, bnsum, bnsq, 0,
            HW, CIN, CI, (size_t)HW * CI, 0, (size_t)HW * CIN);
    }

    if (dual) {
        // BN joins: final of each half needs BOTH halves' z epilogues
        cudaEventRecord(g_eZ1, s1);
        cudaStreamWaitEvent(s0, g_eZ1, 0);
        cudaEventRecord(g_eZ0, s0);
        cudaStreamWaitEvent(s1, g_eZ0, 0);
    }

    for (int h = 0; h < NH; h++) {
        cudaStream_t s = (h == 0) ? s0 : s1;
        final_kernel<<<dim3(HW / 32, CIN / 64, HB), 256, 0, s>>>(x, gamma, beta, out, h * HB);
    }

    if (dual) {
        cudaEventRecord(g_eJ, s1);
        cudaStreamWaitEvent(s0, g_eJ, 0);
    }
}